// round 9
// baseline (speedup 1.0000x reference)
#include <cuda_runtime.h>
#include <cuda_bf16.h>
#include <cstdint>
#include <math.h>

// Problem dims (fixed by setup_inputs)
#define B_ 256
#define D_ 2048
#define H_ 2048
#define K_ 64
#define T_ 32
#define G_ 8192           // 4*H
#define NS 64             // split-K factor for the fe GEMM
#define KC (H_ / NS)      // 32

// ---------------------------------------------------------------------------
// Scratch (device globals; no runtime allocation allowed)
// Weight rows stored GATE-INTERLEAVED: perm row p <- orig row (p&3)*H + (p>>2)
// h_hi/h_lo are PING-PONG buffered across ticks (WAR-race fix).
// ---------------------------------------------------------------------------
__device__ __nv_bfloat16 d_wih_hi[G_ * D_];
__device__ __nv_bfloat16 d_wih_lo[G_ * D_];
__device__ __nv_bfloat16 d_whh_hi[G_ * H_];
__device__ __nv_bfloat16 d_whh_lo[G_ * H_];
__device__ __nv_bfloat16 d_x_hi[B_ * D_];
__device__ __nv_bfloat16 d_x_lo[B_ * D_];
__device__ __nv_bfloat16 d_h_hi[2][B_ * H_];
__device__ __nv_bfloat16 d_h_lo[2][B_ * H_];
__device__ float d_bias[G_];               // permuted b_ih + b_hh
__device__ float d_xg[B_ * G_];            // permuted cols
__device__ float d_h [B_ * H_];
__device__ float d_c [B_ * H_];
__device__ float d_fep[NS * B_ * 2 * K_];

__device__ __forceinline__ uint32_t smem_to_u32(const void* p) {
    uint32_t a;
    asm("{ .reg .u64 t; cvta.to.shared.u64 t, %1; cvt.u32.u64 %0, t; }"
        : "=r"(a) : "l"(p));
    return a;
}

// mma.sync m16n8k16 bf16 -> fp32 accumulate (plain sm_80+ PTX)
#define MMA16816(c, a0, a1, a2, a3, b0, b1) \
    asm volatile( \
        "mma.sync.aligned.m16n8k16.row.col.f32.bf16.bf16.f32 " \
        "{%0,%1,%2,%3}, {%4,%5,%6,%7}, {%8,%9}, {%0,%1,%2,%3};" \
        : "+f"((c)[0]), "+f"((c)[1]), "+f"((c)[2]), "+f"((c)[3]) \
        : "r"(a0), "r"(a1), "r"(a2), "r"(a3), "r"(b0), "r"(b1))

#define LDSM4(r, addr) \
    asm volatile("ldmatrix.sync.aligned.m8n8.x4.shared.b16 {%0,%1,%2,%3}, [%4];" \
        : "=r"((r)[0]), "=r"((r)[1]), "=r"((r)[2]), "=r"((r)[3]) : "r"(addr))

// ---------------------------------------------------------------------------
// Tensor-core split-bf16 GEMM (Xhi*Whi + Xhi*Wlo + Xlo*Whi, fp32 accum)
// CTA tile 32m x 64n, BK=32, 8 warps (warp = 16m x 16n), 3-stage cp.async.
// grid (128 n-tiles, 8 m-tiles) = 1024 CTAs -> 3 CTAs/SM, ~7 tiles/SM
// (wave-quantization waste ~1% vs 13.5% at 256 CTAs).
// gate_mode=0: C[m,n] = acc + bias[n]                     (xg GEMM)
// gate_mode=1: g = acc + xg[m,n]; fused LSTM cell update   (recurrent GEMM)
// ---------------------------------------------------------------------------
#define BK     32
#define NCH    (D_ / BK)       // 64 chunks
#define ROWB   80              // padded row pitch (32 bf16 = 64B data + 16 pad)
#define TILEX  (32 * ROWB)     // 2560  (X tile: 32 rows)
#define TILEW  (64 * ROWB)     // 5120  (W tile: 64 rows)
#define OFF_XHI 0
#define OFF_WHI (2 * TILEX)    // 5120
#define STAGEB  (2 * TILEX + 2 * TILEW)   // 15360
#define NSTAGE  3
#define SMEM_TOTAL (NSTAGE * STAGEB)      // 46080

__global__ __launch_bounds__(256, 3)
void gemm_mma2(const __nv_bfloat16* __restrict__ Xhi,
               const __nv_bfloat16* __restrict__ Xlo,
               const __nv_bfloat16* __restrict__ Whi,
               const __nv_bfloat16* __restrict__ Wlo,
               const float* __restrict__ xg,     // gate_mode=1
               const float* __restrict__ bias,   // gate_mode=0
               float* __restrict__ C,            // gate_mode=0
               float* __restrict__ h,
               float* __restrict__ c,
               __nv_bfloat16* __restrict__ hhi_out,
               __nv_bfloat16* __restrict__ hlo_out,
               int gate_mode)
{
    extern __shared__ __align__(16) char smem[];
    const uint32_t sm0 = smem_to_u32(smem);

    const int tid  = threadIdx.x;
    const int lane = tid & 31;
    const int w    = tid >> 5;
    const int wy   = w & 1;          // m sub-tile (2 x 16)
    const int wx   = w >> 1;         // n sub-tile (4 x 16)
    const int q    = lane & 3;
    const int g    = lane >> 2;
    const int bn   = blockIdx.x * 64;
    const int bm   = blockIdx.y * 32;

    const __nv_bfloat16* xsrc[2] = { Xhi + (size_t)bm * D_, Xlo + (size_t)bm * D_ };
    const __nv_bfloat16* wsrc[2] = { Whi + (size_t)bn * D_, Wlo + (size_t)bn * D_ };

    // ldmatrix per-lane addressing
    const int lrow = (lane & 7) + ((lane >> 3) & 1) * 8;
    const int colh = (lane >> 4) * 16;

    float acc[2][4];
    #pragma unroll
    for (int b = 0; b < 2; b++)
        #pragma unroll
        for (int d = 0; d < 4; d++) acc[b][d] = 0.f;

    // 768 16B-loads per stage: [0,256) X tiles (hi,lo), [256,768) W tiles
#define ISSUE(ch, st) do {                                                    \
    const int _kof = (ch) * BK;                                               \
    _Pragma("unroll")                                                         \
    for (int i = 0; i < 3; i++) {                                             \
        const int _idx = i * 256 + tid;                                       \
        uint32_t _dst; const __nv_bfloat16* _sp;                              \
        if (_idx < 256) {                                                     \
            const int _v = _idx >> 7, _rem = _idx & 127;                      \
            const int _row = _rem >> 2, _qu = _rem & 3;                       \
            _dst = sm0 + (st) * STAGEB + OFF_XHI + _v * TILEX + _row * ROWB + _qu * 16; \
            _sp  = xsrc[_v] + (size_t)_row * D_ + _kof + _qu * 8;             \
        } else {                                                              \
            const int _j = _idx - 256;                                        \
            const int _v = _j >> 8, _rem = _j & 255;                          \
            const int _row = _rem >> 2, _qu = _rem & 3;                       \
            _dst = sm0 + (st) * STAGEB + OFF_WHI + _v * TILEW + _row * ROWB + _qu * 16; \
            _sp  = wsrc[_v] + (size_t)_row * D_ + _kof + _qu * 8;             \
        }                                                                     \
        asm volatile("cp.async.cg.shared.global [%0], [%1], 16;"              \
                     :: "r"(_dst), "l"(_sp));                                 \
    }                                                                         \
    asm volatile("cp.async.commit_group;" ::: "memory");                      \
} while (0)

    ISSUE(0, 0);
    ISSUE(1, 1);

    int st = 0;
    for (int ch = 0; ch < NCH; ch++) {
        if (ch < NCH - 1) asm volatile("cp.async.wait_group 1;" ::: "memory");
        else              asm volatile("cp.async.wait_group 0;" ::: "memory");
        __syncthreads();
        {
            int nst = st + 2; if (nst >= NSTAGE) nst -= NSTAGE;
            if (ch + 2 < NCH) ISSUE(ch + 2, nst);
        }

        const uint32_t stb   = sm0 + st * STAGEB;
        const uint32_t aBase = stb + OFF_XHI + (wy * 16 + lrow) * ROWB + colh;
        const uint32_t bBase = stb + OFF_WHI + (wx * 16 + lrow) * ROWB + colh;

        #pragma unroll
        for (int ks = 0; ks < 2; ks++) {
            uint32_t ah[4], al[4], bh[4], bl[4];
            LDSM4(ah, aBase + ks * 32);
            LDSM4(al, aBase + TILEX + ks * 32);
            LDSM4(bh, bBase + ks * 32);
            LDSM4(bl, bBase + TILEW + ks * 32);
            // Per-acc order hh -> hl -> lh (identical numerics to R8)
            MMA16816(acc[0], ah[0], ah[1], ah[2], ah[3], bh[0], bh[2]);
            MMA16816(acc[1], ah[0], ah[1], ah[2], ah[3], bh[1], bh[3]);
            MMA16816(acc[0], ah[0], ah[1], ah[2], ah[3], bl[0], bl[2]);
            MMA16816(acc[1], ah[0], ah[1], ah[2], ah[3], bl[1], bl[3]);
            MMA16816(acc[0], al[0], al[1], al[2], al[3], bh[0], bh[2]);
            MMA16816(acc[1], al[0], al[1], al[2], al[3], bh[1], bh[3]);
        }
        st = st + 1 >= NSTAGE ? 0 : st + 1;
        // next iteration's __syncthreads protects stage reuse
    }
#undef ISSUE

    // Epilogue
    if (gate_mode == 0) {
        const int m0 = bm + wy * 16 + g;
        #pragma unroll
        for (int j = 0; j < 2; j++) {
            const int n0 = bn + wx * 16 + j * 8 + 2 * q;
            const float d0 = bias[n0], d1 = bias[n0 + 1];
            *(float2*)(C + (size_t)m0 * G_ + n0) =
                make_float2(acc[j][0] + d0, acc[j][1] + d1);
            *(float2*)(C + (size_t)(m0 + 8) * G_ + n0) =
                make_float2(acc[j][2] + d0, acc[j][3] + d1);
        }
        return;
    }

    // gate_mode == 1: fused LSTM cell update (writes ping-pong OUT buffers)
    const int evn = (lane & 1) == 0;   // q even: holds (i,f); q odd: (g,o)
    const int r0  = bm + wy * 16 + g;
    #pragma unroll
    for (int j = 0; j < 2; j++) {
        const int n0 = bn + wx * 16 + j * 8 + 2 * q;
        const float2 p0 = *(const float2*)(xg + (size_t)r0 * G_ + n0);
        const float2 p1 = *(const float2*)(xg + (size_t)(r0 + 8) * G_ + n0);
        float v0 = acc[j][0] + p0.x;
        float v1 = acc[j][1] + p0.y;
        float v2 = acc[j][2] + p1.x;
        float v3 = acc[j][3] + p1.y;

        const float s0 = __shfl_xor_sync(0xffffffffu, v0, 1);
        const float s1 = __shfl_xor_sync(0xffffffffu, v1, 1);
        const float s2 = __shfl_xor_sync(0xffffffffu, v2, 1);
        const float s3 = __shfl_xor_sync(0xffffffffu, v3, 1);

        // even lane handles row r0; odd lane handles row r0+8
        const int   row = evn ? r0 : r0 + 8;
        const float gi = evn ? v0 : s2;
        const float gf = evn ? v1 : s3;
        const float gg = evn ? s0 : v2;
        const float go = evn ? s1 : v3;

        const float iv = 1.f / (1.f + expf(-gi));
        const float fv = 1.f / (1.f + expf(-gf));
        const float gv = tanhf(gg);
        const float ov = 1.f / (1.f + expf(-go));

        const int  u   = (n0 >> 2);               // original hidden unit
        const int  idx = row * H_ + u;
        const float cn = fv * c[idx] + iv * gv;
        c[idx] = cn;
        const float hv = ov * tanhf(cn);
        h[idx] = hv;
        const __nv_bfloat16 hb = __float2bfloat16(hv);
        hhi_out[idx] = hb;
        hlo_out[idx] = __float2bfloat16(hv - __bfloat162float(hb));
    }
}

// ---------------------------------------------------------------------------
// Fused prep: wih decomp (permuted) + whh decomp (permuted) + x decomp + bias
// ---------------------------------------------------------------------------
#define NW (G_ * D_)
__global__ void prep_kernel(const float* __restrict__ x,
                            const float* __restrict__ Wih,
                            const float* __restrict__ Whh,
                            const float* __restrict__ bih,
                            const float* __restrict__ bhh,
                            __nv_bfloat16* __restrict__ wih_hi,
                            __nv_bfloat16* __restrict__ wih_lo,
                            __nv_bfloat16* __restrict__ whh_hi,
                            __nv_bfloat16* __restrict__ whh_lo,
                            __nv_bfloat16* __restrict__ x_hi,
                            __nv_bfloat16* __restrict__ x_lo,
                            float* __restrict__ bias)
{
    const long long i = (long long)blockIdx.x * blockDim.x + threadIdx.x;
    if (i < NW) {
        const int p   = (int)(i / D_);
        const int col = (int)(i - (long long)p * D_);
        const int srow = (p & 3) * H_ + (p >> 2);
        const float v = Wih[(size_t)srow * D_ + col];
        const __nv_bfloat16 hb = __float2bfloat16(v);
        wih_hi[i] = hb;
        wih_lo[i] = __float2bfloat16(v - __bfloat162float(hb));
    } else if (i < 2LL * NW) {
        const long long j = i - NW;
        const int p   = (int)(j / H_);
        const int col = (int)(j - (long long)p * H_);
        const int srow = (p & 3) * H_ + (p >> 2);
        const float v = Whh[(size_t)srow * H_ + col];
        const __nv_bfloat16 hb = __float2bfloat16(v);
        whh_hi[j] = hb;
        whh_lo[j] = __float2bfloat16(v - __bfloat162float(hb));
    } else if (i < 2LL * NW + B_ * D_) {
        const int j = (int)(i - 2LL * NW);
        const float v = x[j];
        const __nv_bfloat16 hb = __float2bfloat16(v);
        x_hi[j] = hb;
        x_lo[j] = __float2bfloat16(v - __bfloat162float(hb));
    } else if (i < 2LL * NW + B_ * D_ + G_) {
        const int p = (int)(i - 2LL * NW - B_ * D_);
        const int o = (p & 3) * H_ + (p >> 2);
        bias[p] = bih[o] + bhh[o];
    }
}

// ---------------------------------------------------------------------------
// t=0 gate: g = xg (h0 = 0), permuted layout
// ---------------------------------------------------------------------------
__global__ void gate0_kernel(const float* __restrict__ xg,
                             float* __restrict__ h,
                             float* __restrict__ c,
                             __nv_bfloat16* __restrict__ hhi,
                             __nv_bfloat16* __restrict__ hlo)
{
    const int idx = blockIdx.x * blockDim.x + threadIdx.x;
    if (idx >= B_ * H_) return;
    const int b = idx / H_;
    const int u = idx - b * H_;
    const float* gr = xg + (size_t)b * G_ + 4 * u;

    const float iv = 1.f / (1.f + expf(-gr[0]));
    const float gv = tanhf(gr[2]);
    const float ov = 1.f / (1.f + expf(-gr[3]));

    const float cn = iv * gv;          // c0 = 0
    c[idx] = cn;
    const float hv = ov * tanhf(cn);
    h[idx] = hv;
    const __nv_bfloat16 hb = __float2bfloat16(hv);
    hhi[idx] = hb;
    hlo[idx] = __float2bfloat16(hv - __bfloat162float(hb));
}

// ---------------------------------------------------------------------------
// fe GEMM, split-K: part[s][m][n] = sum_{k in chunk s} h[m,k] * W_fe[n,k]
// NS=64 -> grid (64, 4) = 256 CTAs (fills all SMs; was 128)
// ---------------------------------------------------------------------------
__global__ __launch_bounds__(256, 1)
void gemm_fe(const float* __restrict__ hmat,
             const float* __restrict__ Wfe,
             float* __restrict__ part)
{
    __shared__ float As[16][68];
    __shared__ float Bs[16][132];

    const int ks   = blockIdx.x;
    const int bm   = blockIdx.y * 64;
    const int koff = ks * KC;
    const int tid  = threadIdx.x;
    const int tx   = tid & 31;
    const int ty   = tid >> 5;

    float acc[8][4];
    #pragma unroll
    for (int i = 0; i < 8; i++)
        #pragma unroll
        for (int j = 0; j < 4; j++) acc[i][j] = 0.f;

    for (int k0 = 0; k0 < KC; k0 += 16) {
        {
            const int row = tid >> 2;
            const int c4  = (tid & 3) * 4;
            float4 v = *(const float4*)(hmat + (size_t)(bm + row) * H_ + koff + k0 + c4);
            As[c4 + 0][row] = v.x;  As[c4 + 1][row] = v.y;
            As[c4 + 2][row] = v.z;  As[c4 + 3][row] = v.w;
        }
        #pragma unroll
        for (int r = 0; r < 2; r++) {
            const int idx = tid + r * 256;
            const int rowb = idx >> 2;
            const int c4  = (idx & 3) * 4;
            float4 v = *(const float4*)(Wfe + (size_t)rowb * H_ + koff + k0 + c4);
            Bs[c4 + 0][rowb] = v.x;  Bs[c4 + 1][rowb] = v.y;
            Bs[c4 + 2][rowb] = v.z;  Bs[c4 + 3][rowb] = v.w;
        }
        __syncthreads();

        #pragma unroll
        for (int kk = 0; kk < 16; kk++) {
            float a[8], b[4];
            #pragma unroll
            for (int i = 0; i < 8; i++) a[i] = As[kk][ty + i * 8];
            #pragma unroll
            for (int j = 0; j < 4; j++) b[j] = Bs[kk][tx + j * 32];
            #pragma unroll
            for (int i = 0; i < 8; i++)
                #pragma unroll
                for (int j = 0; j < 4; j++)
                    acc[i][j] = fmaf(a[i], b[j], acc[i][j]);
        }
        __syncthreads();
    }

    #pragma unroll
    for (int i = 0; i < 8; i++) {
        const int m = bm + ty + i * 8;
        #pragma unroll
        for (int j = 0; j < 4; j++) {
            const int n = tx + j * 32;
            part[((size_t)ks * B_ + m) * (2 * K_) + n] = acc[i][j];
        }
    }
}

// ---------------------------------------------------------------------------
// z epilogue
// ---------------------------------------------------------------------------
__global__ void z_kernel(const float* __restrict__ eps,
                         const float* __restrict__ bfe,
                         const float* __restrict__ part,
                         float* __restrict__ out,
                         int t)
{
    const int idx = blockIdx.x * blockDim.x + threadIdx.x;
    if (idx >= B_ * K_) return;
    const int b = idx / K_;
    const int k = idx - b * K_;

    float mu = bfe[k];
    float sr = bfe[k + K_];
    #pragma unroll 8
    for (int s = 0; s < NS; s++) {
        const float* p = part + ((size_t)s * B_ + b) * (2 * K_);
        mu += p[k];
        sr += p[k + K_];
    }

    const float xv  = sr - 5.f;
    const float sig = (xv > 20.f) ? xv : log1pf(expf(xv));
    const float e   = eps[((size_t)t * B_ + b) * K_ + k];
    const float z   = e * sig + mu;

    const size_t plane = (size_t)B_ * K_ * T_;
    const size_t o = ((size_t)b * K_ + k) * T_ + t;
    out[o]             = z;
    out[o + plane]     = mu;
    out[o + 2 * plane] = sig;
}

__global__ void hc_copy(const float* __restrict__ h,
                        const float* __restrict__ c,
                        float* __restrict__ out)
{
    const int idx = blockIdx.x * blockDim.x + threadIdx.x;
    if (idx >= B_ * H_) return;
    const size_t base = 3 * (size_t)B_ * K_ * T_;
    out[base + idx]           = h[idx];
    out[base + B_ * H_ + idx] = c[idx];
}

// ---------------------------------------------------------------------------
extern "C" void kernel_launch(void* const* d_in, const int* in_sizes, int n_in,
                              void* d_out, int out_size)
{
    const float* x   = (const float*)d_in[0];
    const float* eps = (const float*)d_in[1];
    const float* Wih = (const float*)d_in[2];
    const float* Whh = (const float*)d_in[3];
    const float* bih = (const float*)d_in[4];
    const float* bhh = (const float*)d_in[5];
    const float* Wfe = (const float*)d_in[6];
    const float* bfe = (const float*)d_in[7];
    float* out = (float*)d_out;

    __nv_bfloat16 *wih_hi, *wih_lo, *whh_hi, *whh_lo, *x_hi, *x_lo, *hhi2, *hlo2;
    float *xg, *h, *c, *fep, *bias;
    cudaGetSymbolAddress((void**)&wih_hi, d_wih_hi);
    cudaGetSymbolAddress((void**)&wih_lo, d_wih_lo);
    cudaGetSymbolAddress((void**)&whh_hi, d_whh_hi);
    cudaGetSymbolAddress((void**)&whh_lo, d_whh_lo);
    cudaGetSymbolAddress((void**)&x_hi,   d_x_hi);
    cudaGetSymbolAddress((void**)&x_lo,   d_x_lo);
    cudaGetSymbolAddress((void**)&hhi2,   d_h_hi);
    cudaGetSymbolAddress((void**)&hlo2,   d_h_lo);
    cudaGetSymbolAddress((void**)&xg,   d_xg);
    cudaGetSymbolAddress((void**)&h,    d_h);
    cudaGetSymbolAddress((void**)&c,    d_c);
    cudaGetSymbolAddress((void**)&fep,  d_fep);
    cudaGetSymbolAddress((void**)&bias, d_bias);

    __nv_bfloat16* hhi_buf[2] = { hhi2, hhi2 + B_ * H_ };
    __nv_bfloat16* hlo_buf[2] = { hlo2, hlo2 + B_ * H_ };

    cudaFuncSetAttribute(gemm_mma2, cudaFuncAttributeMaxDynamicSharedMemorySize,
                         SMEM_TOTAL);

    const dim3 gTc(G_ / 64, B_ / 32);      // (128, 8) = 1024 CTAs
    const dim3 gFe(NS, B_ / 64);           // (64, 4) = 256 CTAs
    const int  eltBlocks = (B_ * H_ + 255) / 256;
    const int  zBlocks   = (B_ * K_ + 255) / 256;

    // Fused prep (single launch)
    const long long prepN = 2LL * NW + B_ * D_ + G_;
    prep_kernel<<<(int)((prepN + 255) / 256), 256>>>(
        x, Wih, Whh, bih, bhh,
        wih_hi, wih_lo, whh_hi, whh_lo, x_hi, x_lo, bias);

    // xg = x @ Wih_perm^T + bias_perm   (permuted cols)
    gemm_mma2<<<gTc, 256, SMEM_TOTAL>>>(x_hi, x_lo, wih_hi, wih_lo,
                                        nullptr, bias, xg,
                                        nullptr, nullptr, nullptr, nullptr, 0);

    for (int t = 0; t < T_; t++) {
        if (t == 0) {
            gate0_kernel<<<eltBlocks, 256>>>(xg, h, c, hhi_buf[0], hlo_buf[0]);
        } else {
            // read tick (t-1)'s h from buf[(t-1)&1], write tick t's h to buf[t&1]
            gemm_mma2<<<gTc, 256, SMEM_TOTAL>>>(hhi_buf[(t - 1) & 1], hlo_buf[(t - 1) & 1],
                                                whh_hi, whh_lo,
                                                xg, nullptr, nullptr,
                                                h, c, hhi_buf[t & 1], hlo_buf[t & 1], 1);
        }
        gemm_fe<<<gFe, 256>>>(h, Wfe, fep);
        z_kernel<<<zBlocks, 256>>>(eps, bfe, fep, out, t);
    }

    hc_copy<<<eltBlocks, 256>>>(h, c, out);
}

// round 10
// speedup vs baseline: 1.1261x; 1.1261x over previous
#include <cuda_runtime.h>
#include <cuda_bf16.h>
#include <cstdint>
#include <math.h>

// Problem dims (fixed by setup_inputs)
#define B_ 256
#define D_ 2048
#define H_ 2048
#define K_ 64
#define T_ 32
#define G_ 8192           // 4*H
#define NS 64             // split-K factor for the fe GEMM
#define KC (H_ / NS)      // 32

// ---------------------------------------------------------------------------
// Scratch (device globals; no runtime allocation allowed)
// Weight rows stored GATE-INTERLEAVED: perm row p <- orig row (p&3)*H + (p>>2)
// h, h_hi, h_lo are PING-PONG buffered across ticks (WAR safety for both the
// sequential GEMM chain and the concurrent fe/z side stream).
// ---------------------------------------------------------------------------
__device__ __nv_bfloat16 d_wih_hi[G_ * D_];
__device__ __nv_bfloat16 d_wih_lo[G_ * D_];
__device__ __nv_bfloat16 d_whh_hi[G_ * H_];
__device__ __nv_bfloat16 d_whh_lo[G_ * H_];
__device__ __nv_bfloat16 d_x_hi[B_ * D_];
__device__ __nv_bfloat16 d_x_lo[B_ * D_];
__device__ __nv_bfloat16 d_h_hi[2][B_ * H_];
__device__ __nv_bfloat16 d_h_lo[2][B_ * H_];
__device__ float d_bias[G_];               // permuted b_ih + b_hh
__device__ float d_xg[B_ * G_];            // permuted cols
__device__ float d_h [2][B_ * H_];
__device__ float d_c [B_ * H_];
__device__ float d_fep[NS * B_ * 2 * K_];

__device__ __forceinline__ uint32_t smem_to_u32(const void* p) {
    uint32_t a;
    asm("{ .reg .u64 t; cvta.to.shared.u64 t, %1; cvt.u32.u64 %0, t; }"
        : "=r"(a) : "l"(p));
    return a;
}

// mma.sync m16n8k16 bf16 -> fp32 accumulate (plain sm_80+ PTX)
#define MMA16816(c, a0, a1, a2, a3, b0, b1) \
    asm volatile( \
        "mma.sync.aligned.m16n8k16.row.col.f32.bf16.bf16.f32 " \
        "{%0,%1,%2,%3}, {%4,%5,%6,%7}, {%8,%9}, {%0,%1,%2,%3};" \
        : "+f"((c)[0]), "+f"((c)[1]), "+f"((c)[2]), "+f"((c)[3]) \
        : "r"(a0), "r"(a1), "r"(a2), "r"(a3), "r"(b0), "r"(b1))

#define LDSM4(r, addr) \
    asm volatile("ldmatrix.sync.aligned.m8n8.x4.shared.b16 {%0,%1,%2,%3}, [%4];" \
        : "=r"((r)[0]), "=r"((r)[1]), "=r"((r)[2]), "=r"((r)[3]) : "r"(addr))

// ---------------------------------------------------------------------------
// Tensor-core split-bf16 GEMM (Xhi*Whi + Xhi*Wlo + Xlo*Whi, fp32 accum)
// CTA tile 64m x 128n, BK=32, 8 warps (warp = 32m x 32n), 3-stage cp.async.
// grid (64 n-tiles, 4 m-tiles) = 256 CTAs -> 2 CTAs/SM  (R8 best config).
// gate_mode=0: C[m,n] = acc + bias[n]                     (xg GEMM)
// gate_mode=1: g = acc + xg[m,n]; fused LSTM cell update   (recurrent GEMM)
// ---------------------------------------------------------------------------
#define BK     32
#define NCH    (D_ / BK)       // 64 chunks
#define ROWB   80              // padded row pitch (32 bf16 = 64B data + 16 pad)
#define TILEA  (64 * ROWB)     // 5120  (X tile: 64 rows)
#define TILEW  (128 * ROWB)    // 10240 (W tile: 128 rows)
#define OFF_XHI 0
#define OFF_WHI (2 * TILEA)
#define STAGEB  (2 * TILEA + 2 * TILEW)   // 30720
#define NSTAGE  3
#define SMEM_TOTAL (NSTAGE * STAGEB)      // 92160

__global__ __launch_bounds__(256, 2)
void gemm_mma2(const __nv_bfloat16* __restrict__ Xhi,
               const __nv_bfloat16* __restrict__ Xlo,
               const __nv_bfloat16* __restrict__ Whi,
               const __nv_bfloat16* __restrict__ Wlo,
               const float* __restrict__ xg,     // gate_mode=1
               const float* __restrict__ bias,   // gate_mode=0
               float* __restrict__ C,            // gate_mode=0
               float* __restrict__ h_out,
               float* __restrict__ c,
               __nv_bfloat16* __restrict__ hhi_out,
               __nv_bfloat16* __restrict__ hlo_out,
               int gate_mode)
{
    extern __shared__ __align__(16) char smem[];
    const uint32_t sm0 = smem_to_u32(smem);

    const int tid  = threadIdx.x;
    const int lane = tid & 31;
    const int w    = tid >> 5;
    const int wy   = w & 1;          // m sub-tile (2 x 32)
    const int wx   = w >> 1;         // n sub-tile (4 x 32)
    const int q    = lane & 3;
    const int g    = lane >> 2;
    const int bn   = blockIdx.x * 128;
    const int bm   = blockIdx.y * 64;

    const __nv_bfloat16* xsrc[2] = { Xhi + (size_t)bm * D_, Xlo + (size_t)bm * D_ };
    const __nv_bfloat16* wsrc[2] = { Whi + (size_t)bn * D_, Wlo + (size_t)bn * D_ };

    // ldmatrix per-lane addressing
    const int lrow = (lane & 7) + ((lane >> 3) & 1) * 8;
    const int colh = (lane >> 4) * 16;

    float acc[2][4][4];
    #pragma unroll
    for (int a = 0; a < 2; a++)
        #pragma unroll
        for (int b = 0; b < 4; b++)
            #pragma unroll
            for (int d = 0; d < 4; d++) acc[a][b][d] = 0.f;

    // 1536 16B-loads per stage: [0,512) X tiles (hi,lo), [512,1536) W tiles
#define ISSUE(ch, st) do {                                                    \
    const int _kof = (ch) * BK;                                               \
    _Pragma("unroll")                                                         \
    for (int i = 0; i < 6; i++) {                                             \
        const int _idx = i * 256 + tid;                                       \
        uint32_t _dst; const __nv_bfloat16* _sp;                              \
        if (_idx < 512) {                                                     \
            const int _v = _idx >> 8, _rem = _idx & 255;                      \
            const int _row = _rem >> 2, _qu = _rem & 3;                       \
            _dst = sm0 + (st) * STAGEB + OFF_XHI + _v * TILEA + _row * ROWB + _qu * 16; \
            _sp  = xsrc[_v] + (size_t)_row * D_ + _kof + _qu * 8;             \
        } else {                                                              \
            const int _j = _idx - 512;                                        \
            const int _v = _j >> 9, _rem = _j & 511;                          \
            const int _row = _rem >> 2, _qu = _rem & 3;                       \
            _dst = sm0 + (st) * STAGEB + OFF_WHI + _v * TILEW + _row * ROWB + _qu * 16; \
            _sp  = wsrc[_v] + (size_t)_row * D_ + _kof + _qu * 8;             \
        }                                                                     \
        asm volatile("cp.async.cg.shared.global [%0], [%1], 16;"              \
                     :: "r"(_dst), "l"(_sp));                                 \
    }                                                                         \
    asm volatile("cp.async.commit_group;" ::: "memory");                      \
} while (0)

    ISSUE(0, 0);
    ISSUE(1, 1);

    int st = 0;
    for (int ch = 0; ch < NCH; ch++) {
        if (ch < NCH - 1) asm volatile("cp.async.wait_group 1;" ::: "memory");
        else              asm volatile("cp.async.wait_group 0;" ::: "memory");
        __syncthreads();
        {
            int nst = st + 2; if (nst >= NSTAGE) nst -= NSTAGE;
            if (ch + 2 < NCH) ISSUE(ch + 2, nst);
        }

        const uint32_t stb = sm0 + st * STAGEB;
        const uint32_t aHi = stb + OFF_XHI + (wy * 32 + lrow) * ROWB + colh;
        const uint32_t bHi = stb + OFF_WHI + (wx * 32 + lrow) * ROWB + colh;

        #pragma unroll
        for (int ks = 0; ks < 2; ks++) {
            uint32_t ah[2][4], al[2][4], bh[2][4], bl[2][4];
            #pragma unroll
            for (int mb = 0; mb < 2; mb++) {
                LDSM4(ah[mb], aHi + mb * 16 * ROWB + ks * 32);
                LDSM4(al[mb], aHi + TILEA + mb * 16 * ROWB + ks * 32);
            }
            #pragma unroll
            for (int t2 = 0; t2 < 2; t2++) {
                LDSM4(bh[t2], bHi + t2 * 16 * ROWB + ks * 32);
                LDSM4(bl[t2], bHi + TILEW + t2 * 16 * ROWB + ks * 32);
            }
            // Term-major issue: 8 independent MMAs per term
            #pragma unroll
            for (int t2 = 0; t2 < 2; t2++)
                #pragma unroll
                for (int mb = 0; mb < 2; mb++) {
                    MMA16816(acc[mb][t2 * 2],     ah[mb][0], ah[mb][1], ah[mb][2], ah[mb][3], bh[t2][0], bh[t2][2]);
                    MMA16816(acc[mb][t2 * 2 + 1], ah[mb][0], ah[mb][1], ah[mb][2], ah[mb][3], bh[t2][1], bh[t2][3]);
                }
            #pragma unroll
            for (int t2 = 0; t2 < 2; t2++)
                #pragma unroll
                for (int mb = 0; mb < 2; mb++) {
                    MMA16816(acc[mb][t2 * 2],     ah[mb][0], ah[mb][1], ah[mb][2], ah[mb][3], bl[t2][0], bl[t2][2]);
                    MMA16816(acc[mb][t2 * 2 + 1], ah[mb][0], ah[mb][1], ah[mb][2], ah[mb][3], bl[t2][1], bl[t2][3]);
                }
            #pragma unroll
            for (int t2 = 0; t2 < 2; t2++)
                #pragma unroll
                for (int mb = 0; mb < 2; mb++) {
                    MMA16816(acc[mb][t2 * 2],     al[mb][0], al[mb][1], al[mb][2], al[mb][3], bh[t2][0], bh[t2][2]);
                    MMA16816(acc[mb][t2 * 2 + 1], al[mb][0], al[mb][1], al[mb][2], al[mb][3], bh[t2][1], bh[t2][3]);
                }
        }
        st = st + 1 >= NSTAGE ? 0 : st + 1;
        // next iteration's __syncthreads protects stage reuse
    }
#undef ISSUE

    // Epilogue
    if (gate_mode == 0) {
        #pragma unroll
        for (int mb = 0; mb < 2; mb++) {
            const int m0 = bm + wy * 32 + mb * 16 + g;
            #pragma unroll
            for (int j = 0; j < 4; j++) {
                const int n0 = bn + wx * 32 + j * 8 + 2 * q;
                const float d0 = bias[n0], d1 = bias[n0 + 1];
                *(float2*)(C + (size_t)m0 * G_ + n0) =
                    make_float2(acc[mb][j][0] + d0, acc[mb][j][1] + d1);
                *(float2*)(C + (size_t)(m0 + 8) * G_ + n0) =
                    make_float2(acc[mb][j][2] + d0, acc[mb][j][3] + d1);
            }
        }
        return;
    }

    // gate_mode == 1: fused LSTM cell update (writes ping-pong OUT buffers)
    const int evn = (lane & 1) == 0;   // q even: holds (i,f); q odd: (g,o)
    #pragma unroll
    for (int mb = 0; mb < 2; mb++) {
        const int r0 = bm + wy * 32 + mb * 16 + g;
        #pragma unroll
        for (int j = 0; j < 4; j++) {
            const int n0 = bn + wx * 32 + j * 8 + 2 * q;
            const float2 p0 = *(const float2*)(xg + (size_t)r0 * G_ + n0);
            const float2 p1 = *(const float2*)(xg + (size_t)(r0 + 8) * G_ + n0);
            float v0 = acc[mb][j][0] + p0.x;
            float v1 = acc[mb][j][1] + p0.y;
            float v2 = acc[mb][j][2] + p1.x;
            float v3 = acc[mb][j][3] + p1.y;

            const float s0 = __shfl_xor_sync(0xffffffffu, v0, 1);
            const float s1 = __shfl_xor_sync(0xffffffffu, v1, 1);
            const float s2 = __shfl_xor_sync(0xffffffffu, v2, 1);
            const float s3 = __shfl_xor_sync(0xffffffffu, v3, 1);

            // even lane handles row r0; odd lane handles row r0+8
            const int   row = evn ? r0 : r0 + 8;
            const float gi = evn ? v0 : s2;
            const float gf = evn ? v1 : s3;
            const float gg = evn ? s0 : v2;
            const float go = evn ? s1 : v3;

            const float iv = 1.f / (1.f + expf(-gi));
            const float fv = 1.f / (1.f + expf(-gf));
            const float gv = tanhf(gg);
            const float ov = 1.f / (1.f + expf(-go));

            const int  u   = (n0 >> 2);               // original hidden unit
            const int  idx = row * H_ + u;
            const float cn = fv * c[idx] + iv * gv;
            c[idx] = cn;
            const float hv = ov * tanhf(cn);
            h_out[idx] = hv;
            const __nv_bfloat16 hb = __float2bfloat16(hv);
            hhi_out[idx] = hb;
            hlo_out[idx] = __float2bfloat16(hv - __bfloat162float(hb));
        }
    }
}

// ---------------------------------------------------------------------------
// Fused prep: wih decomp (permuted) + whh decomp (permuted) + x decomp + bias
// ---------------------------------------------------------------------------
#define NW (G_ * D_)
__global__ void prep_kernel(const float* __restrict__ x,
                            const float* __restrict__ Wih,
                            const float* __restrict__ Whh,
                            const float* __restrict__ bih,
                            const float* __restrict__ bhh,
                            __nv_bfloat16* __restrict__ wih_hi,
                            __nv_bfloat16* __restrict__ wih_lo,
                            __nv_bfloat16* __restrict__ whh_hi,
                            __nv_bfloat16* __restrict__ whh_lo,
                            __nv_bfloat16* __restrict__ x_hi,
                            __nv_bfloat16* __restrict__ x_lo,
                            float* __restrict__ bias)
{
    const long long i = (long long)blockIdx.x * blockDim.x + threadIdx.x;
    if (i < NW) {
        const int p   = (int)(i / D_);
        const int col = (int)(i - (long long)p * D_);
        const int srow = (p & 3) * H_ + (p >> 2);
        const float v = Wih[(size_t)srow * D_ + col];
        const __nv_bfloat16 hb = __float2bfloat16(v);
        wih_hi[i] = hb;
        wih_lo[i] = __float2bfloat16(v - __bfloat162float(hb));
    } else if (i < 2LL * NW) {
        const long long j = i - NW;
        const int p   = (int)(j / H_);
        const int col = (int)(j - (long long)p * H_);
        const int srow = (p & 3) * H_ + (p >> 2);
        const float v = Whh[(size_t)srow * H_ + col];
        const __nv_bfloat16 hb = __float2bfloat16(v);
        whh_hi[j] = hb;
        whh_lo[j] = __float2bfloat16(v - __bfloat162float(hb));
    } else if (i < 2LL * NW + B_ * D_) {
        const int j = (int)(i - 2LL * NW);
        const float v = x[j];
        const __nv_bfloat16 hb = __float2bfloat16(v);
        x_hi[j] = hb;
        x_lo[j] = __float2bfloat16(v - __bfloat162float(hb));
    } else if (i < 2LL * NW + B_ * D_ + G_) {
        const int p = (int)(i - 2LL * NW - B_ * D_);
        const int o = (p & 3) * H_ + (p >> 2);
        bias[p] = bih[o] + bhh[o];
    }
}

// ---------------------------------------------------------------------------
// t=0 gate: g = xg (h0 = 0), permuted layout
// ---------------------------------------------------------------------------
__global__ void gate0_kernel(const float* __restrict__ xg,
                             float* __restrict__ h,
                             float* __restrict__ c,
                             __nv_bfloat16* __restrict__ hhi,
                             __nv_bfloat16* __restrict__ hlo)
{
    const int idx = blockIdx.x * blockDim.x + threadIdx.x;
    if (idx >= B_ * H_) return;
    const int b = idx / H_;
    const int u = idx - b * H_;
    const float* gr = xg + (size_t)b * G_ + 4 * u;

    const float iv = 1.f / (1.f + expf(-gr[0]));
    const float gv = tanhf(gr[2]);
    const float ov = 1.f / (1.f + expf(-gr[3]));

    const float cn = iv * gv;          // c0 = 0
    c[idx] = cn;
    const float hv = ov * tanhf(cn);
    h[idx] = hv;
    const __nv_bfloat16 hb = __float2bfloat16(hv);
    hhi[idx] = hb;
    hlo[idx] = __float2bfloat16(hv - __bfloat162float(hb));
}

// ---------------------------------------------------------------------------
// fe GEMM, split-K: part[s][m][n] = sum_{k in chunk s} h[m,k] * W_fe[n,k]
// NS=64 -> grid (64, 4) = 256 CTAs
// ---------------------------------------------------------------------------
__global__ __launch_bounds__(256, 1)
void gemm_fe(const float* __restrict__ hmat,
             const float* __restrict__ Wfe,
             float* __restrict__ part)
{
    __shared__ float As[16][68];
    __shared__ float Bs[16][132];

    const int ks   = blockIdx.x;
    const int bm   = blockIdx.y * 64;
    const int koff = ks * KC;
    const int tid  = threadIdx.x;
    const int tx   = tid & 31;
    const int ty   = tid >> 5;

    float acc[8][4];
    #pragma unroll
    for (int i = 0; i < 8; i++)
        #pragma unroll
        for (int j = 0; j < 4; j++) acc[i][j] = 0.f;

    for (int k0 = 0; k0 < KC; k0 += 16) {
        {
            const int row = tid >> 2;
            const int c4  = (tid & 3) * 4;
            float4 v = *(const float4*)(hmat + (size_t)(bm + row) * H_ + koff + k0 + c4);
            As[c4 + 0][row] = v.x;  As[c4 + 1][row] = v.y;
            As[c4 + 2][row] = v.z;  As[c4 + 3][row] = v.w;
        }
        #pragma unroll
        for (int r = 0; r < 2; r++) {
            const int idx = tid + r * 256;
            const int rowb = idx >> 2;
            const int c4  = (idx & 3) * 4;
            float4 v = *(const float4*)(Wfe + (size_t)rowb * H_ + koff + k0 + c4);
            Bs[c4 + 0][rowb] = v.x;  Bs[c4 + 1][rowb] = v.y;
            Bs[c4 + 2][rowb] = v.z;  Bs[c4 + 3][rowb] = v.w;
        }
        __syncthreads();

        #pragma unroll
        for (int kk = 0; kk < 16; kk++) {
            float a[8], b[4];
            #pragma unroll
            for (int i = 0; i < 8; i++) a[i] = As[kk][ty + i * 8];
            #pragma unroll
            for (int j = 0; j < 4; j++) b[j] = Bs[kk][tx + j * 32];
            #pragma unroll
            for (int i = 0; i < 8; i++)
                #pragma unroll
                for (int j = 0; j < 4; j++)
                    acc[i][j] = fmaf(a[i], b[j], acc[i][j]);
        }
        __syncthreads();
    }

    #pragma unroll
    for (int i = 0; i < 8; i++) {
        const int m = bm + ty + i * 8;
        #pragma unroll
        for (int j = 0; j < 4; j++) {
            const int n = tx + j * 32;
            part[((size_t)ks * B_ + m) * (2 * K_) + n] = acc[i][j];
        }
    }
}

// ---------------------------------------------------------------------------
// z epilogue
// ---------------------------------------------------------------------------
__global__ void z_kernel(const float* __restrict__ eps,
                         const float* __restrict__ bfe,
                         const float* __restrict__ part,
                         float* __restrict__ out,
                         int t)
{
    const int idx = blockIdx.x * blockDim.x + threadIdx.x;
    if (idx >= B_ * K_) return;
    const int b = idx / K_;
    const int k = idx - b * K_;

    float mu = bfe[k];
    float sr = bfe[k + K_];
    #pragma unroll 8
    for (int s = 0; s < NS; s++) {
        const float* p = part + ((size_t)s * B_ + b) * (2 * K_);
        mu += p[k];
        sr += p[k + K_];
    }

    const float xv  = sr - 5.f;
    const float sig = (xv > 20.f) ? xv : log1pf(expf(xv));
    const float e   = eps[((size_t)t * B_ + b) * K_ + k];
    const float z   = e * sig + mu;

    const size_t plane = (size_t)B_ * K_ * T_;
    const size_t o = ((size_t)b * K_ + k) * T_ + t;
    out[o]             = z;
    out[o + plane]     = mu;
    out[o + 2 * plane] = sig;
}

__global__ void hc_copy(const float* __restrict__ h,
                        const float* __restrict__ c,
                        float* __restrict__ out)
{
    const int idx = blockIdx.x * blockDim.x + threadIdx.x;
    if (idx >= B_ * H_) return;
    const size_t base = 3 * (size_t)B_ * K_ * T_;
    out[base + idx]           = h[idx];
    out[base + B_ * H_ + idx] = c[idx];
}

// ---------------------------------------------------------------------------
extern "C" void kernel_launch(void* const* d_in, const int* in_sizes, int n_in,
                              void* d_out, int out_size)
{
    const float* x   = (const float*)d_in[0];
    const float* eps = (const float*)d_in[1];
    const float* Wih = (const float*)d_in[2];
    const float* Whh = (const float*)d_in[3];
    const float* bih = (const float*)d_in[4];
    const float* bhh = (const float*)d_in[5];
    const float* Wfe = (const float*)d_in[6];
    const float* bfe = (const float*)d_in[7];
    float* out = (float*)d_out;

    __nv_bfloat16 *wih_hi, *wih_lo, *whh_hi, *whh_lo, *x_hi, *x_lo, *hhi2, *hlo2;
    float *xg, *h2, *c, *fep, *bias;
    cudaGetSymbolAddress((void**)&wih_hi, d_wih_hi);
    cudaGetSymbolAddress((void**)&wih_lo, d_wih_lo);
    cudaGetSymbolAddress((void**)&whh_hi, d_whh_hi);
    cudaGetSymbolAddress((void**)&whh_lo, d_whh_lo);
    cudaGetSymbolAddress((void**)&x_hi,   d_x_hi);
    cudaGetSymbolAddress((void**)&x_lo,   d_x_lo);
    cudaGetSymbolAddress((void**)&hhi2,   d_h_hi);
    cudaGetSymbolAddress((void**)&hlo2,   d_h_lo);
    cudaGetSymbolAddress((void**)&xg,   d_xg);
    cudaGetSymbolAddress((void**)&h2,   d_h);
    cudaGetSymbolAddress((void**)&c,    d_c);
    cudaGetSymbolAddress((void**)&fep,  d_fep);
    cudaGetSymbolAddress((void**)&bias, d_bias);

    __nv_bfloat16* hhi_buf[2] = { hhi2, hhi2 + B_ * H_ };
    __nv_bfloat16* hlo_buf[2] = { hlo2, hlo2 + B_ * H_ };
    float*         h_buf[2]   = { h2,   h2   + B_ * H_ };

    // One-time host resources (streams/events are not device memory)
    static cudaStream_t s2 = nullptr;
    static cudaEvent_t  evG[T_], evF[T_];
    if (s2 == nullptr) {
        cudaStreamCreateWithFlags(&s2, cudaStreamNonBlocking);
        for (int t = 0; t < T_; t++) {
            cudaEventCreateWithFlags(&evG[t], cudaEventDisableTiming);
            cudaEventCreateWithFlags(&evF[t], cudaEventDisableTiming);
        }
        cudaFuncSetAttribute(gemm_mma2,
                             cudaFuncAttributeMaxDynamicSharedMemorySize,
                             SMEM_TOTAL);
    }

    const dim3 gTc(G_ / 128, B_ / 64);     // (64, 4) = 256 CTAs
    const dim3 gFe(NS, B_ / 64);           // (64, 4) = 256 CTAs
    const int  eltBlocks = (B_ * H_ + 255) / 256;
    const int  zBlocks   = (B_ * K_ + 255) / 256;

    // Fused prep (single launch)
    const long long prepN = 2LL * NW + B_ * D_ + G_;
    prep_kernel<<<(int)((prepN + 255) / 256), 256>>>(
        x, Wih, Whh, bih, bhh,
        wih_hi, wih_lo, whh_hi, whh_lo, x_hi, x_lo, bias);

    // xg = x @ Wih_perm^T + bias_perm   (permuted cols)
    gemm_mma2<<<gTc, 256, SMEM_TOTAL>>>(x_hi, x_lo, wih_hi, wih_lo,
                                        nullptr, bias, xg,
                                        nullptr, nullptr, nullptr, nullptr, 0);

    for (int t = 0; t < T_; t++) {
        // GEMM(t) rewrites h_buf[t&1], which fe(t-2) reads on s2 -> back edge
        if (t >= 2) cudaStreamWaitEvent(0, evF[t - 2], 0);

        if (t == 0) {
            gate0_kernel<<<eltBlocks, 256>>>(xg, h_buf[0], c,
                                             hhi_buf[0], hlo_buf[0]);
        } else {
            // read tick (t-1)'s h from buf[(t-1)&1], write tick t to buf[t&1]
            gemm_mma2<<<gTc, 256, SMEM_TOTAL>>>(
                hhi_buf[(t - 1) & 1], hlo_buf[(t - 1) & 1],
                whh_hi, whh_lo,
                xg, nullptr, nullptr,
                h_buf[t & 1], c, hhi_buf[t & 1], hlo_buf[t & 1], 1);
        }
        cudaEventRecord(evG[t], 0);

        // fe/z for tick t on the side stream, overlapped with GEMM(t+1)
        cudaStreamWaitEvent(s2, evG[t], 0);
        gemm_fe<<<gFe, 256, 0, s2>>>(h_buf[t & 1], Wfe, fep);
        z_kernel<<<zBlocks, 256, 0, s2>>>(eps, bfe, fep, out, t);
        cudaEventRecord(evF[t], s2);
    }

    // Join side stream, then final (h, c) copy
    cudaStreamWaitEvent(0, evF[T_ - 1], 0);
    hc_copy<<<eltBlocks, 256>>>(h_buf[(T_ - 1) & 1], c, out);
}

// round 12
// speedup vs baseline: 1.1475x; 1.0190x over previous
#include <cuda_runtime.h>
#include <cuda_bf16.h>
#include <cstdint>
#include <math.h>

// Problem dims (fixed by setup_inputs)
#define B_ 256
#define D_ 2048
#define H_ 2048
#define K_ 64
#define T_ 32
#define G_ 8192           // 4*H
#define GA 8320           // augmented N: 4*H + 2*K (fused fe columns)
#define NS 64             // split-K factor for the final-tick fe GEMM
#define KC (H_ / NS)      // 32

// ---------------------------------------------------------------------------
// Scratch (device globals; no runtime allocation allowed)
// W_hh/W_ih rows GATE-INTERLEAVED: perm row p <- orig row (p&3)*H + (p>>2)
// W_fe rows MU/SIG-INTERLEAVED:    perm row p <- orig row (p&1)*K + (p>>1)
// h, h_hi, h_lo PING-PONG buffered across ticks.
// ---------------------------------------------------------------------------
__device__ __nv_bfloat16 d_wih_hi[G_ * D_];
__device__ __nv_bfloat16 d_wih_lo[G_ * D_];
__device__ __nv_bfloat16 d_whh_hi[G_ * H_];
__device__ __nv_bfloat16 d_whh_lo[G_ * H_];
__device__ __nv_bfloat16 d_wfe_hi[2 * K_ * H_];
__device__ __nv_bfloat16 d_wfe_lo[2 * K_ * H_];
__device__ __nv_bfloat16 d_x_hi[B_ * D_];
__device__ __nv_bfloat16 d_x_lo[B_ * D_];
__device__ __nv_bfloat16 d_h_hi[2][B_ * H_];
__device__ __nv_bfloat16 d_h_lo[2][B_ * H_];
__device__ float d_bias[G_];               // permuted b_ih + b_hh
__device__ float d_xg[B_ * G_];            // permuted cols
__device__ float d_h [2][B_ * H_];
__device__ float d_c [B_ * H_];
__device__ float d_fep[NS * B_ * 2 * K_];

__device__ __forceinline__ uint32_t smem_to_u32(const void* p) {
    uint32_t a;
    asm("{ .reg .u64 t; cvta.to.shared.u64 t, %1; cvt.u32.u64 %0, t; }"
        : "=r"(a) : "l"(p));
    return a;
}

// mma.sync m16n8k16 bf16 -> fp32 accumulate (plain sm_80+ PTX)
#define MMA16816(c, a0, a1, a2, a3, b0, b1) \
    asm volatile( \
        "mma.sync.aligned.m16n8k16.row.col.f32.bf16.bf16.f32 " \
        "{%0,%1,%2,%3}, {%4,%5,%6,%7}, {%8,%9}, {%0,%1,%2,%3};" \
        : "+f"((c)[0]), "+f"((c)[1]), "+f"((c)[2]), "+f"((c)[3]) \
        : "r"(a0), "r"(a1), "r"(a2), "r"(a3), "r"(b0), "r"(b1))

#define LDSM4(r, addr) \
    asm volatile("ldmatrix.sync.aligned.m8n8.x4.shared.b16 {%0,%1,%2,%3}, [%4];" \
        : "=r"((r)[0]), "=r"((r)[1]), "=r"((r)[2]), "=r"((r)[3]) : "r"(addr))

// ---------------------------------------------------------------------------
// Tensor-core split-bf16 GEMM (Xhi*Whi + Xhi*Wlo + Xlo*Whi, fp32 accum)
// CTA tile 64m x 128n, BK=32, 8 warps (warp = 32m x 32n), 3-stage cp.async.
// gate_mode=0: grid (64,4):  C[m,n] = acc + bias[n]          (xg GEMM)
// gate_mode=1: grid (65,4):  n-tiles 0..63: g = acc + xg -> fused LSTM update;
//              n-tile 64 (bn=G_): fused fe -> z/mu/sig for tick tprev.
// ---------------------------------------------------------------------------
#define BK     32
#define NCH    (D_ / BK)       // 64 chunks
#define ROWB   80              // padded row pitch (32 bf16 = 64B data + 16 pad)
#define TILEA  (64 * ROWB)     // 5120  (X tile: 64 rows)
#define TILEW  (128 * ROWB)    // 10240 (W tile: 128 rows)
#define OFF_XHI 0
#define OFF_WHI (2 * TILEA)
#define STAGEB  (2 * TILEA + 2 * TILEW)   // 30720
#define NSTAGE  3
#define SMEM_TOTAL (NSTAGE * STAGEB)      // 92160

__global__ __launch_bounds__(256, 2)
void gemm_mma2(const __nv_bfloat16* __restrict__ Xhi,
               const __nv_bfloat16* __restrict__ Xlo,
               const __nv_bfloat16* __restrict__ Whi,
               const __nv_bfloat16* __restrict__ Wlo,
               const __nv_bfloat16* __restrict__ Fhi,   // wfe hi (gate_mode=1)
               const __nv_bfloat16* __restrict__ Flo,   // wfe lo
               const float* __restrict__ xg,     // gate_mode=1
               const float* __restrict__ bias,   // gate_mode=0
               float* __restrict__ C,            // gate_mode=0
               float* __restrict__ h_out,
               float* __restrict__ c,
               __nv_bfloat16* __restrict__ hhi_out,
               __nv_bfloat16* __restrict__ hlo_out,
               const float* __restrict__ eps,    // fused fe
               const float* __restrict__ bfe,    // fused fe
               float* __restrict__ zout,         // fused fe
               int tprev,                        // fused fe tick index
               int gate_mode)
{
    extern __shared__ __align__(16) char smem[];
    const uint32_t sm0 = smem_to_u32(smem);

    const int tid  = threadIdx.x;
    const int lane = tid & 31;
    const int w    = tid >> 5;
    const int wy   = w & 1;          // m sub-tile (2 x 32)
    const int wx   = w >> 1;         // n sub-tile (4 x 32)
    const int q    = lane & 3;
    const int g    = lane >> 2;
    const int bn   = blockIdx.x * 128;
    const int bm   = blockIdx.y * 64;
    const int feTile = (bn >= G_);

    const __nv_bfloat16* xsrc[2] = { Xhi + (size_t)bm * D_, Xlo + (size_t)bm * D_ };
    const __nv_bfloat16* wsrc[2] = {
        feTile ? Fhi : Whi + (size_t)bn * D_,
        feTile ? Flo : Wlo + (size_t)bn * D_
    };

    // ldmatrix per-lane addressing
    const int lrow = (lane & 7) + ((lane >> 3) & 1) * 8;
    const int colh = (lane >> 4) * 16;

    float acc[2][4][4];
    #pragma unroll
    for (int a = 0; a < 2; a++)
        #pragma unroll
        for (int b = 0; b < 4; b++)
            #pragma unroll
            for (int d = 0; d < 4; d++) acc[a][b][d] = 0.f;

    // 1536 16B-loads per stage: [0,512) X tiles (hi,lo), [512,1536) W tiles
#define ISSUE(ch, st) do {                                                    \
    const int _kof = (ch) * BK;                                               \
    _Pragma("unroll")                                                         \
    for (int i = 0; i < 6; i++) {                                             \
        const int _idx = i * 256 + tid;                                       \
        uint32_t _dst; const __nv_bfloat16* _sp;                              \
        if (_idx < 512) {                                                     \
            const int _v = _idx >> 8, _rem = _idx & 255;                      \
            const int _row = _rem >> 2, _qu = _rem & 3;                       \
            _dst = sm0 + (st) * STAGEB + OFF_XHI + _v * TILEA + _row * ROWB + _qu * 16; \
            _sp  = xsrc[_v] + (size_t)_row * D_ + _kof + _qu * 8;             \
        } else {                                                              \
            const int _j = _idx - 512;                                        \
            const int _v = _j >> 9, _rem = _j & 511;                          \
            const int _row = _rem >> 2, _qu = _rem & 3;                       \
            _dst = sm0 + (st) * STAGEB + OFF_WHI + _v * TILEW + _row * ROWB + _qu * 16; \
            _sp  = wsrc[_v] + (size_t)_row * D_ + _kof + _qu * 8;             \
        }                                                                     \
        asm volatile("cp.async.cg.shared.global [%0], [%1], 16;"              \
                     :: "r"(_dst), "l"(_sp));                                 \
    }                                                                         \
    asm volatile("cp.async.commit_group;" ::: "memory");                      \
} while (0)

    ISSUE(0, 0);
    ISSUE(1, 1);

    int st = 0;
    for (int ch = 0; ch < NCH; ch++) {
        if (ch < NCH - 1) asm volatile("cp.async.wait_group 1;" ::: "memory");
        else              asm volatile("cp.async.wait_group 0;" ::: "memory");
        __syncthreads();
        {
            int nst = st + 2; if (nst >= NSTAGE) nst -= NSTAGE;
            if (ch + 2 < NCH) ISSUE(ch + 2, nst);
        }

        const uint32_t stb = sm0 + st * STAGEB;
        const uint32_t aHi = stb + OFF_XHI + (wy * 32 + lrow) * ROWB + colh;
        const uint32_t bHi = stb + OFF_WHI + (wx * 32 + lrow) * ROWB + colh;

        #pragma unroll
        for (int ks = 0; ks < 2; ks++) {
            uint32_t ah[2][4], al[2][4], bh[2][4], bl[2][4];
            #pragma unroll
            for (int mb = 0; mb < 2; mb++) {
                LDSM4(ah[mb], aHi + mb * 16 * ROWB + ks * 32);
                LDSM4(al[mb], aHi + TILEA + mb * 16 * ROWB + ks * 32);
            }
            #pragma unroll
            for (int t2 = 0; t2 < 2; t2++) {
                LDSM4(bh[t2], bHi + t2 * 16 * ROWB + ks * 32);
                LDSM4(bl[t2], bHi + TILEW + t2 * 16 * ROWB + ks * 32);
            }
            // Term-major issue: 8 independent MMAs per term
            #pragma unroll
            for (int t2 = 0; t2 < 2; t2++)
                #pragma unroll
                for (int mb = 0; mb < 2; mb++) {
                    MMA16816(acc[mb][t2 * 2],     ah[mb][0], ah[mb][1], ah[mb][2], ah[mb][3], bh[t2][0], bh[t2][2]);
                    MMA16816(acc[mb][t2 * 2 + 1], ah[mb][0], ah[mb][1], ah[mb][2], ah[mb][3], bh[t2][1], bh[t2][3]);
                }
            #pragma unroll
            for (int t2 = 0; t2 < 2; t2++)
                #pragma unroll
                for (int mb = 0; mb < 2; mb++) {
                    MMA16816(acc[mb][t2 * 2],     ah[mb][0], ah[mb][1], ah[mb][2], ah[mb][3], bl[t2][0], bl[t2][2]);
                    MMA16816(acc[mb][t2 * 2 + 1], ah[mb][0], ah[mb][1], ah[mb][2], ah[mb][3], bl[t2][1], bl[t2][3]);
                }
            #pragma unroll
            for (int t2 = 0; t2 < 2; t2++)
                #pragma unroll
                for (int mb = 0; mb < 2; mb++) {
                    MMA16816(acc[mb][t2 * 2],     al[mb][0], al[mb][1], al[mb][2], al[mb][3], bh[t2][0], bh[t2][2]);
                    MMA16816(acc[mb][t2 * 2 + 1], al[mb][0], al[mb][1], al[mb][2], al[mb][3], bh[t2][1], bh[t2][3]);
                }
        }
        st = st + 1 >= NSTAGE ? 0 : st + 1;
        // next iteration's __syncthreads protects stage reuse
    }
#undef ISSUE

    // ---------------- Epilogues ----------------
    if (gate_mode == 0) {
        #pragma unroll
        for (int mb = 0; mb < 2; mb++) {
            const int m0 = bm + wy * 32 + mb * 16 + g;
            #pragma unroll
            for (int j = 0; j < 4; j++) {
                const int n0 = bn + wx * 32 + j * 8 + 2 * q;
                const float d0 = bias[n0], d1 = bias[n0 + 1];
                *(float2*)(C + (size_t)m0 * G_ + n0) =
                    make_float2(acc[mb][j][0] + d0, acc[mb][j][1] + d1);
                *(float2*)(C + (size_t)(m0 + 8) * G_ + n0) =
                    make_float2(acc[mb][j][2] + d0, acc[mb][j][3] + d1);
            }
        }
        return;
    }

    if (feTile) {
        // Fused fe/z epilogue: cols (2k, 2k+1) = (mu_k partial, sig_k partial)
        // for tick tprev (the h this GEMM consumed).
        const size_t plane = (size_t)B_ * K_ * T_;
        #pragma unroll
        for (int mb = 0; mb < 2; mb++) {
            const int r0 = bm + wy * 32 + mb * 16 + g;
            #pragma unroll
            for (int j = 0; j < 4; j++) {
                const int col = wx * 32 + j * 8 + 2 * q;   // 0..127, even
                const int k   = col >> 1;
                const float bmu = bfe[k];
                const float bsr = bfe[K_ + k];
                #pragma unroll
                for (int rr = 0; rr < 2; rr++) {
                    const int   b  = r0 + rr * 8;
                    const float mu = acc[mb][j][rr * 2 + 0] + bmu;
                    const float xv = acc[mb][j][rr * 2 + 1] + bsr - 5.f;
                    const float sig = (xv > 20.f) ? xv : log1pf(expf(xv));
                    const float e  = eps[((size_t)tprev * B_ + b) * K_ + k];
                    const size_t o = ((size_t)b * K_ + k) * T_ + tprev;
                    zout[o]             = e * sig + mu;
                    zout[o + plane]     = mu;
                    zout[o + 2 * plane] = sig;
                }
            }
        }
        return;
    }

    // LSTM gate epilogue (writes ping-pong OUT buffers)
    const int evn = (lane & 1) == 0;   // q even: holds (i,f); q odd: (g,o)
    #pragma unroll
    for (int mb = 0; mb < 2; mb++) {
        const int r0 = bm + wy * 32 + mb * 16 + g;
        #pragma unroll
        for (int j = 0; j < 4; j++) {
            const int n0 = bn + wx * 32 + j * 8 + 2 * q;
            const float2 p0 = *(const float2*)(xg + (size_t)r0 * G_ + n0);
            const float2 p1 = *(const float2*)(xg + (size_t)(r0 + 8) * G_ + n0);
            float v0 = acc[mb][j][0] + p0.x;
            float v1 = acc[mb][j][1] + p0.y;
            float v2 = acc[mb][j][2] + p1.x;
            float v3 = acc[mb][j][3] + p1.y;

            const float s0 = __shfl_xor_sync(0xffffffffu, v0, 1);
            const float s1 = __shfl_xor_sync(0xffffffffu, v1, 1);
            const float s2 = __shfl_xor_sync(0xffffffffu, v2, 1);
            const float s3 = __shfl_xor_sync(0xffffffffu, v3, 1);

            // even lane handles row r0; odd lane handles row r0+8
            const int   row = evn ? r0 : r0 + 8;
            const float gi = evn ? v0 : s2;
            const float gf = evn ? v1 : s3;
            const float gg = evn ? s0 : v2;
            const float go = evn ? s1 : v3;

            const float iv = 1.f / (1.f + expf(-gi));
            const float fv = 1.f / (1.f + expf(-gf));
            const float gv = tanhf(gg);
            const float ov = 1.f / (1.f + expf(-go));

            const int  u   = (n0 >> 2);               // original hidden unit
            const int  idx = row * H_ + u;
            const float cn = fv * c[idx] + iv * gv;
            c[idx] = cn;
            const float hv = ov * tanhf(cn);
            h_out[idx] = hv;
            const __nv_bfloat16 hb = __float2bfloat16(hv);
            hhi_out[idx] = hb;
            hlo_out[idx] = __float2bfloat16(hv - __bfloat162float(hb));
        }
    }
}

// ---------------------------------------------------------------------------
// Fused prep (single launch, stream 0):
// wih decomp (gate-permuted) + whh decomp (gate-permuted) +
// wfe decomp (mu/sig-interleaved) + x decomp + bias
// ---------------------------------------------------------------------------
#define NW (G_ * D_)
__global__ void prep_kernel(const float* __restrict__ x,
                            const float* __restrict__ Wih,
                            const float* __restrict__ Whh,
                            const float* __restrict__ Wfe,
                            const float* __restrict__ bih,
                            const float* __restrict__ bhh,
                            __nv_bfloat16* __restrict__ wih_hi,
                            __nv_bfloat16* __restrict__ wih_lo,
                            __nv_bfloat16* __restrict__ whh_hi,
                            __nv_bfloat16* __restrict__ whh_lo,
                            __nv_bfloat16* __restrict__ wfe_hi,
                            __nv_bfloat16* __restrict__ wfe_lo,
                            __nv_bfloat16* __restrict__ x_hi,
                            __nv_bfloat16* __restrict__ x_lo,
                            float* __restrict__ bias)
{
    const long long i = (long long)blockIdx.x * blockDim.x + threadIdx.x;
    if (i < NW) {
        const int p   = (int)(i / D_);
        const int col = (int)(i - (long long)p * D_);
        const int srow = (p & 3) * H_ + (p >> 2);
        const float v = Wih[(size_t)srow * D_ + col];
        const __nv_bfloat16 hb = __float2bfloat16(v);
        wih_hi[i] = hb;
        wih_lo[i] = __float2bfloat16(v - __bfloat162float(hb));
    } else if (i < 2LL * NW) {
        const long long j = i - NW;
        const int p   = (int)(j / H_);
        const int col = (int)(j - (long long)p * H_);
        const int srow = (p & 3) * H_ + (p >> 2);
        const float v = Whh[(size_t)srow * H_ + col];
        const __nv_bfloat16 hb = __float2bfloat16(v);
        whh_hi[j] = hb;
        whh_lo[j] = __float2bfloat16(v - __bfloat162float(hb));
    } else if (i < 2LL * NW + 2LL * K_ * H_) {
        const int j   = (int)(i - 2LL * NW);
        const int p   = j / H_;          // 0..127
        const int col = j - p * H_;
        const int srow = (p & 1) ? (K_ + (p >> 1)) : (p >> 1);   // mu/sig interleave
        const float v = Wfe[(size_t)srow * H_ + col];
        const __nv_bfloat16 hb = __float2bfloat16(v);
        wfe_hi[j] = hb;
        wfe_lo[j] = __float2bfloat16(v - __bfloat162float(hb));
    } else if (i < 2LL * NW + 2LL * K_ * H_ + B_ * D_) {
        const int j = (int)(i - 2LL * NW - 2LL * K_ * H_);
        const float v = x[j];
        const __nv_bfloat16 hb = __float2bfloat16(v);
        x_hi[j] = hb;
        x_lo[j] = __float2bfloat16(v - __bfloat162float(hb));
    } else if (i < 2LL * NW + 2LL * K_ * H_ + B_ * D_ + G_) {
        const int p = (int)(i - 2LL * NW - 2LL * K_ * H_ - B_ * D_);
        const int o = (p & 3) * H_ + (p >> 2);
        bias[p] = bih[o] + bhh[o];
    }
}

// ---------------------------------------------------------------------------
// t=0 gate: g = xg (h0 = 0), permuted layout
// ---------------------------------------------------------------------------
__global__ void gate0_kernel(const float* __restrict__ xg,
                             float* __restrict__ h,
                             float* __restrict__ c,
                             __nv_bfloat16* __restrict__ hhi,
                             __nv_bfloat16* __restrict__ hlo)
{
    const int idx = blockIdx.x * blockDim.x + threadIdx.x;
    if (idx >= B_ * H_) return;
    const int b = idx / H_;
    const int u = idx - b * H_;
    const float* gr = xg + (size_t)b * G_ + 4 * u;

    const float iv = 1.f / (1.f + expf(-gr[0]));
    const float gv = tanhf(gr[2]);
    const float ov = 1.f / (1.f + expf(-gr[3]));

    const float cn = iv * gv;          // c0 = 0
    c[idx] = cn;
    const float hv = ov * tanhf(cn);
    h[idx] = hv;
    const __nv_bfloat16 hb = __float2bfloat16(hv);
    hhi[idx] = hb;
    hlo[idx] = __float2bfloat16(hv - __bfloat162float(hb));
}

// ---------------------------------------------------------------------------
// Final-tick fe GEMM, split-K (fp32; runs once after the loop)
// ---------------------------------------------------------------------------
__global__ __launch_bounds__(256, 1)
void gemm_fe(const float* __restrict__ hmat,
             const float* __restrict__ Wfe,
             float* __restrict__ part)
{
    __shared__ float As[16][68];
    __shared__ float Bs[16][132];

    const int ks   = blockIdx.x;
    const int bm   = blockIdx.y * 64;
    const int koff = ks * KC;
    const int tid  = threadIdx.x;
    const int tx   = tid & 31;
    const int ty   = tid >> 5;

    float acc[8][4];
    #pragma unroll
    for (int i = 0; i < 8; i++)
        #pragma unroll
        for (int j = 0; j < 4; j++) acc[i][j] = 0.f;

    for (int k0 = 0; k0 < KC; k0 += 16) {
        {
            const int row = tid >> 2;
            const int c4  = (tid & 3) * 4;
            float4 v = *(const float4*)(hmat + (size_t)(bm + row) * H_ + koff + k0 + c4);
            As[c4 + 0][row] = v.x;  As[c4 + 1][row] = v.y;
            As[c4 + 2][row] = v.z;  As[c4 + 3][row] = v.w;
        }
        #pragma unroll
        for (int r = 0; r < 2; r++) {
            const int idx = tid + r * 256;
            const int rowb = idx >> 2;
            const int c4  = (idx & 3) * 4;
            float4 v = *(const float4*)(Wfe + (size_t)rowb * H_ + koff + k0 + c4);
            Bs[c4 + 0][rowb] = v.x;  Bs[c4 + 1][rowb] = v.y;
            Bs[c4 + 2][rowb] = v.z;  Bs[c4 + 3][rowb] = v.w;
        }
        __syncthreads();

        #pragma unroll
        for (int kk = 0; kk < 16; kk++) {
            float a[8], b[4];
            #pragma unroll
            for (int i = 0; i < 8; i++) a[i] = As[kk][ty + i * 8];
            #pragma unroll
            for (int j = 0; j < 4; j++) b[j] = Bs[kk][tx + j * 32];
            #pragma unroll
            for (int i = 0; i < 8; i++)
                #pragma unroll
                for (int j = 0; j < 4; j++)
                    acc[i][j] = fmaf(a[i], b[j], acc[i][j]);
        }
        __syncthreads();
    }

    #pragma unroll
    for (int i = 0; i < 8; i++) {
        const int m = bm + ty + i * 8;
        #pragma unroll
        for (int j = 0; j < 4; j++) {
            const int n = tx + j * 32;
            part[((size_t)ks * B_ + m) * (2 * K_) + n] = acc[i][j];
        }
    }
}

__global__ void z_kernel(const float* __restrict__ eps,
                         const float* __restrict__ bfe,
                         const float* __restrict__ part,
                         float* __restrict__ out,
                         int t)
{
    const int idx = blockIdx.x * blockDim.x + threadIdx.x;
    if (idx >= B_ * K_) return;
    const int b = idx / K_;
    const int k = idx - b * K_;

    float mu = bfe[k];
    float sr = bfe[k + K_];
    #pragma unroll 8
    for (int s = 0; s < NS; s++) {
        const float* p = part + ((size_t)s * B_ + b) * (2 * K_);
        mu += p[k];
        sr += p[k + K_];
    }

    const float xv  = sr - 5.f;
    const float sig = (xv > 20.f) ? xv : log1pf(expf(xv));
    const float e   = eps[((size_t)t * B_ + b) * K_ + k];
    const float z   = e * sig + mu;

    const size_t plane = (size_t)B_ * K_ * T_;
    const size_t o = ((size_t)b * K_ + k) * T_ + t;
    out[o]             = z;
    out[o + plane]     = mu;
    out[o + 2 * plane] = sig;
}

__global__ void hc_copy(const float* __restrict__ h,
                        const float* __restrict__ c,
                        float* __restrict__ out)
{
    const int idx = blockIdx.x * blockDim.x + threadIdx.x;
    if (idx >= B_ * H_) return;
    const size_t base = 3 * (size_t)B_ * K_ * T_;
    out[base + idx]           = h[idx];
    out[base + B_ * H_ + idx] = c[idx];
}

// ---------------------------------------------------------------------------
extern "C" void kernel_launch(void* const* d_in, const int* in_sizes, int n_in,
                              void* d_out, int out_size)
{
    const float* x   = (const float*)d_in[0];
    const float* eps = (const float*)d_in[1];
    const float* Wih = (const float*)d_in[2];
    const float* Whh = (const float*)d_in[3];
    const float* bih = (const float*)d_in[4];
    const float* bhh = (const float*)d_in[5];
    const float* Wfe = (const float*)d_in[6];
    const float* bfe = (const float*)d_in[7];
    float* out = (float*)d_out;

    __nv_bfloat16 *wih_hi, *wih_lo, *whh_hi, *whh_lo, *wfe_hi, *wfe_lo;
    __nv_bfloat16 *x_hi, *x_lo, *hhi2, *hlo2;
    float *xg, *h2, *c, *fep, *bias;
    cudaGetSymbolAddress((void**)&wih_hi, d_wih_hi);
    cudaGetSymbolAddress((void**)&wih_lo, d_wih_lo);
    cudaGetSymbolAddress((void**)&whh_hi, d_whh_hi);
    cudaGetSymbolAddress((void**)&whh_lo, d_whh_lo);
    cudaGetSymbolAddress((void**)&wfe_hi, d_wfe_hi);
    cudaGetSymbolAddress((void**)&wfe_lo, d_wfe_lo);
    cudaGetSymbolAddress((void**)&x_hi,   d_x_hi);
    cudaGetSymbolAddress((void**)&x_lo,   d_x_lo);
    cudaGetSymbolAddress((void**)&hhi2,   d_h_hi);
    cudaGetSymbolAddress((void**)&hlo2,   d_h_lo);
    cudaGetSymbolAddress((void**)&xg,   d_xg);
    cudaGetSymbolAddress((void**)&h2,   d_h);
    cudaGetSymbolAddress((void**)&c,    d_c);
    cudaGetSymbolAddress((void**)&fep,  d_fep);
    cudaGetSymbolAddress((void**)&bias, d_bias);

    __nv_bfloat16* hhi_buf[2] = { hhi2, hhi2 + B_ * H_ };
    __nv_bfloat16* hlo_buf[2] = { hlo2, hlo2 + B_ * H_ };
    float*         h_buf[2]   = { h2,   h2   + B_ * H_ };

    static int inited = 0;
    if (!inited) {
        cudaFuncSetAttribute(gemm_mma2,
                             cudaFuncAttributeMaxDynamicSharedMemorySize,
                             SMEM_TOTAL);
        inited = 1;
    }

    const dim3 gTc0(G_ / 128, B_ / 64);    // (64, 4)  xg GEMM
    const dim3 gTc1(GA / 128, B_ / 64);    // (65, 4)  recurrent GEMM + fused fe
    const dim3 gFe(NS, B_ / 64);           // final-tick fe
    const int  eltBlocks = (B_ * H_ + 255) / 256;
    const int  zBlocks   = (B_ * K_ + 255) / 256;

    // Fused prep (single launch, stream 0 — graph-capture safe)
    const long long prepN = 2LL * NW + 2LL * K_ * H_ + B_ * D_ + G_;
    prep_kernel<<<(int)((prepN + 255) / 256), 256>>>(
        x, Wih, Whh, Wfe, bih, bhh,
        wih_hi, wih_lo, whh_hi, whh_lo, wfe_hi, wfe_lo, x_hi, x_lo, bias);

    // xg = x @ Wih_perm^T + bias_perm   (permuted cols)
    gemm_mma2<<<gTc0, 256, SMEM_TOTAL>>>(x_hi, x_lo, wih_hi, wih_lo,
                                         nullptr, nullptr,
                                         nullptr, bias, xg,
                                         nullptr, nullptr, nullptr, nullptr,
                                         nullptr, nullptr, nullptr, 0, 0);

    for (int t = 0; t < T_; t++) {
        if (t == 0) {
            gate0_kernel<<<eltBlocks, 256>>>(xg, h_buf[0], c,
                                             hhi_buf[0], hlo_buf[0]);
        } else {
            // GEMM(t): gates(t) from h(t-1)  +  fused fe/z for tick t-1
            gemm_mma2<<<gTc1, 256, SMEM_TOTAL>>>(
                hhi_buf[(t - 1) & 1], hlo_buf[(t - 1) & 1],
                whh_hi, whh_lo, wfe_hi, wfe_lo,
                xg, nullptr, nullptr,
                h_buf[t & 1], c, hhi_buf[t & 1], hlo_buf[t & 1],
                eps, bfe, out, t - 1, 1);
        }
    }

    // Final tick's fe/z (t = T-1) + (h, c) copy
    gemm_fe<<<gFe, 256>>>(h_buf[(T_ - 1) & 1], Wfe, fep);
    z_kernel<<<zBlocks, 256>>>(eps, bfe, fep, out, T_ - 1);
    hc_copy<<<eltBlocks, 256>>>(h_buf[(T_ - 1) & 1], c, out);
}

// round 13
// speedup vs baseline: 1.1570x; 1.0083x over previous
#include <cuda_runtime.h>
#include <cuda_bf16.h>
#include <cstdint>
#include <math.h>

// Problem dims (fixed by setup_inputs)
#define B_ 256
#define D_ 2048
#define H_ 2048
#define K_ 64
#define T_ 32
#define G_ 8192           // 4*H
#define GA 8320           // augmented N: 4*H + 2*K (fused fe columns)
#define NS 64             // split-K factor for the final-tick fe GEMM
#define KC (H_ / NS)      // 32

// ---------------------------------------------------------------------------
// Scratch (device globals; no runtime allocation allowed)
// W_hh/W_ih rows GATE-INTERLEAVED: perm row p <- orig row (p&3)*H + (p>>2)
// W_fe rows MU/SIG-INTERLEAVED:    perm row p <- orig row (p&1)*K + (p>>1)
// h, h_hi, h_lo PING-PONG buffered across ticks.
// ---------------------------------------------------------------------------
__device__ __nv_bfloat16 d_wih_hi[G_ * D_];
__device__ __nv_bfloat16 d_wih_lo[G_ * D_];
__device__ __nv_bfloat16 d_whh_hi[G_ * H_];
__device__ __nv_bfloat16 d_whh_lo[G_ * H_];
__device__ __nv_bfloat16 d_wfe_hi[2 * K_ * H_];
__device__ __nv_bfloat16 d_wfe_lo[2 * K_ * H_];
__device__ __nv_bfloat16 d_x_hi[B_ * D_];
__device__ __nv_bfloat16 d_x_lo[B_ * D_];
__device__ __nv_bfloat16 d_h_hi[2][B_ * H_];
__device__ __nv_bfloat16 d_h_lo[2][B_ * H_];
__device__ float d_bias[G_];               // permuted b_ih + b_hh
__device__ float d_xg[B_ * G_];            // permuted cols
__device__ float d_h [2][B_ * H_];
__device__ float d_c [B_ * H_];
__device__ float d_fep[NS * B_ * 2 * K_];

__device__ __forceinline__ uint32_t smem_to_u32(const void* p) {
    uint32_t a;
    asm("{ .reg .u64 t; cvta.to.shared.u64 t, %1; cvt.u32.u64 %0, t; }"
        : "=r"(a) : "l"(p));
    return a;
}

// mma.sync m16n8k16 bf16 -> fp32 accumulate (plain sm_80+ PTX)
#define MMA16816(c, a0, a1, a2, a3, b0, b1) \
    asm volatile( \
        "mma.sync.aligned.m16n8k16.row.col.f32.bf16.bf16.f32 " \
        "{%0,%1,%2,%3}, {%4,%5,%6,%7}, {%8,%9}, {%0,%1,%2,%3};" \
        : "+f"((c)[0]), "+f"((c)[1]), "+f"((c)[2]), "+f"((c)[3]) \
        : "r"(a0), "r"(a1), "r"(a2), "r"(a3), "r"(b0), "r"(b1))

#define LDSM4(r, addr) \
    asm volatile("ldmatrix.sync.aligned.m8n8.x4.shared.b16 {%0,%1,%2,%3}, [%4];" \
        : "=r"((r)[0]), "=r"((r)[1]), "=r"((r)[2]), "=r"((r)[3]) : "r"(addr))

// ---------------------------------------------------------------------------
// Tensor-core split-bf16 GEMM (Xhi*Whi + Xhi*Wlo + Xlo*Whi, fp32 accum)
// CTA tile 64m x 128n, BK=32, 8 warps (warp = 32m x 32n), 3-stage cp.async.
// cp.async addressing hoisted: 6 (ptr, smem-ofs) pairs per thread, +BK/chunk.
// gate_mode=0: grid (64,4): writes xg[m,n]=acc+bias AND does t=0 cell update
// gate_mode=1: grid (65,4): n-tiles 0..63: g = acc + xg -> fused LSTM update;
//              n-tile 64 (bn=G_): fused fe -> z/mu/sig for tick tprev.
// ---------------------------------------------------------------------------
#define BK     32
#define NCH    (D_ / BK)       // 64 chunks
#define ROWB   80              // padded row pitch (32 bf16 = 64B data + 16 pad)
#define TILEA  (64 * ROWB)     // 5120  (X tile: 64 rows)
#define TILEW  (128 * ROWB)    // 10240 (W tile: 128 rows)
#define OFF_XHI 0
#define OFF_WHI (2 * TILEA)
#define STAGEB  (2 * TILEA + 2 * TILEW)   // 30720
#define NSTAGE  3
#define SMEM_TOTAL (NSTAGE * STAGEB)      // 92160

__global__ __launch_bounds__(256, 2)
void gemm_mma2(const __nv_bfloat16* __restrict__ Xhi,
               const __nv_bfloat16* __restrict__ Xlo,
               const __nv_bfloat16* __restrict__ Whi,
               const __nv_bfloat16* __restrict__ Wlo,
               const __nv_bfloat16* __restrict__ Fhi,   // wfe hi (gate_mode=1)
               const __nv_bfloat16* __restrict__ Flo,   // wfe lo
               const float* __restrict__ xg,     // gate_mode=1 (read)
               const float* __restrict__ bias,   // gate_mode=0
               float* __restrict__ C,            // gate_mode=0 (xg write)
               float* __restrict__ h_out,
               float* __restrict__ c,
               __nv_bfloat16* __restrict__ hhi_out,
               __nv_bfloat16* __restrict__ hlo_out,
               const float* __restrict__ eps,    // fused fe
               const float* __restrict__ bfe,    // fused fe
               float* __restrict__ zout,         // fused fe
               int tprev,                        // fused fe tick index
               int gate_mode)
{
    extern __shared__ __align__(16) char smem[];
    const uint32_t sm0 = smem_to_u32(smem);

    const int tid  = threadIdx.x;
    const int lane = tid & 31;
    const int w    = tid >> 5;
    const int wy   = w & 1;          // m sub-tile (2 x 32)
    const int wx   = w >> 1;         // n sub-tile (4 x 32)
    const int q    = lane & 3;
    const int g    = lane >> 2;
    const int bn   = blockIdx.x * 128;
    const int bm   = blockIdx.y * 64;
    const int feTile = (bn >= G_);

    // Hoisted cp.async addressing: 6 (global ptr, smem offset) pairs
    const __nv_bfloat16* gsrc[6];
    uint32_t dofs[6];
    {
        const __nv_bfloat16* xsrc[2] = { Xhi + (size_t)bm * D_, Xlo + (size_t)bm * D_ };
        const __nv_bfloat16* wsrc[2] = {
            feTile ? Fhi : Whi + (size_t)bn * D_,
            feTile ? Flo : Wlo + (size_t)bn * D_
        };
        #pragma unroll
        for (int i = 0; i < 6; i++) {
            const int idx = i * 256 + tid;
            if (idx < 512) {
                const int v = idx >> 8, rem = idx & 255;
                const int row = rem >> 2, qu = rem & 3;
                dofs[i] = OFF_XHI + v * TILEA + row * ROWB + qu * 16;
                gsrc[i] = xsrc[v] + (size_t)row * D_ + qu * 8;
            } else {
                const int j = idx - 512;
                const int v = j >> 9, rem = j & 511;
                const int row = rem >> 2, qu = rem & 3;
                dofs[i] = OFF_WHI + v * TILEW + row * ROWB + qu * 16;
                gsrc[i] = wsrc[v] + (size_t)row * D_ + qu * 8;
            }
        }
    }

    // ldmatrix per-lane addressing
    const int lrow = (lane & 7) + ((lane >> 3) & 1) * 8;
    const int colh = (lane >> 4) * 16;

    float acc[2][4][4];
    #pragma unroll
    for (int a = 0; a < 2; a++)
        #pragma unroll
        for (int b = 0; b < 4; b++)
            #pragma unroll
            for (int d = 0; d < 4; d++) acc[a][b][d] = 0.f;

#define ISSUE(st) do {                                                        \
    const uint32_t _stb = sm0 + (st) * STAGEB;                                \
    _Pragma("unroll")                                                         \
    for (int i = 0; i < 6; i++) {                                             \
        asm volatile("cp.async.cg.shared.global [%0], [%1], 16;"              \
                     :: "r"(_stb + dofs[i]), "l"(gsrc[i]));                   \
        gsrc[i] += BK;                                                        \
    }                                                                         \
    asm volatile("cp.async.commit_group;" ::: "memory");                      \
} while (0)

    ISSUE(0);
    ISSUE(1);

    int st = 0, st_issue = 2;
    for (int ch = 0; ch < NCH; ch++) {
        if (ch < NCH - 1) asm volatile("cp.async.wait_group 1;" ::: "memory");
        else              asm volatile("cp.async.wait_group 0;" ::: "memory");
        __syncthreads();
        if (ch + 2 < NCH) {
            ISSUE(st_issue);
            st_issue = st_issue + 1 >= NSTAGE ? 0 : st_issue + 1;
        }

        const uint32_t stb = sm0 + st * STAGEB;
        const uint32_t aHi = stb + OFF_XHI + (wy * 32 + lrow) * ROWB + colh;
        const uint32_t bHi = stb + OFF_WHI + (wx * 32 + lrow) * ROWB + colh;

        #pragma unroll
        for (int ks = 0; ks < 2; ks++) {
            uint32_t ah[2][4], al[2][4], bh[2][4], bl[2][4];
            #pragma unroll
            for (int mb = 0; mb < 2; mb++) {
                LDSM4(ah[mb], aHi + mb * 16 * ROWB + ks * 32);
                LDSM4(al[mb], aHi + TILEA + mb * 16 * ROWB + ks * 32);
            }
            #pragma unroll
            for (int t2 = 0; t2 < 2; t2++) {
                LDSM4(bh[t2], bHi + t2 * 16 * ROWB + ks * 32);
                LDSM4(bl[t2], bHi + TILEW + t2 * 16 * ROWB + ks * 32);
            }
            // Term-major issue: 8 independent MMAs per term
            #pragma unroll
            for (int t2 = 0; t2 < 2; t2++)
                #pragma unroll
                for (int mb = 0; mb < 2; mb++) {
                    MMA16816(acc[mb][t2 * 2],     ah[mb][0], ah[mb][1], ah[mb][2], ah[mb][3], bh[t2][0], bh[t2][2]);
                    MMA16816(acc[mb][t2 * 2 + 1], ah[mb][0], ah[mb][1], ah[mb][2], ah[mb][3], bh[t2][1], bh[t2][3]);
                }
            #pragma unroll
            for (int t2 = 0; t2 < 2; t2++)
                #pragma unroll
                for (int mb = 0; mb < 2; mb++) {
                    MMA16816(acc[mb][t2 * 2],     ah[mb][0], ah[mb][1], ah[mb][2], ah[mb][3], bl[t2][0], bl[t2][2]);
                    MMA16816(acc[mb][t2 * 2 + 1], ah[mb][0], ah[mb][1], ah[mb][2], ah[mb][3], bl[t2][1], bl[t2][3]);
                }
            #pragma unroll
            for (int t2 = 0; t2 < 2; t2++)
                #pragma unroll
                for (int mb = 0; mb < 2; mb++) {
                    MMA16816(acc[mb][t2 * 2],     al[mb][0], al[mb][1], al[mb][2], al[mb][3], bh[t2][0], bh[t2][2]);
                    MMA16816(acc[mb][t2 * 2 + 1], al[mb][0], al[mb][1], al[mb][2], al[mb][3], bh[t2][1], bh[t2][3]);
                }
        }
        st = st + 1 >= NSTAGE ? 0 : st + 1;
        // next iteration's __syncthreads protects stage reuse
    }
#undef ISSUE

    // ---------------- Epilogues ----------------
    if (gate_mode == 1 && feTile) {
        // Fused fe/z epilogue: cols (2k, 2k+1) = (mu_k partial, sig_k partial)
        const size_t plane = (size_t)B_ * K_ * T_;
        #pragma unroll
        for (int mb = 0; mb < 2; mb++) {
            const int r0 = bm + wy * 32 + mb * 16 + g;
            #pragma unroll
            for (int j = 0; j < 4; j++) {
                const int col = wx * 32 + j * 8 + 2 * q;   // 0..127, even
                const int k   = col >> 1;
                const float bmu = bfe[k];
                const float bsr = bfe[K_ + k];
                #pragma unroll
                for (int rr = 0; rr < 2; rr++) {
                    const int   b  = r0 + rr * 8;
                    const float mu = acc[mb][j][rr * 2 + 0] + bmu;
                    const float xv = acc[mb][j][rr * 2 + 1] + bsr - 5.f;
                    const float sig = (xv > 20.f) ? xv : log1pf(expf(xv));
                    const float e  = eps[((size_t)tprev * B_ + b) * K_ + k];
                    const size_t o = ((size_t)b * K_ + k) * T_ + tprev;
                    zout[o]             = e * sig + mu;
                    zout[o + plane]     = mu;
                    zout[o + 2 * plane] = sig;
                }
            }
        }
        return;
    }

    // Gate epilogue (both modes). mode 0: v = acc + bias, write xg, cp = 0.
    //                             mode 1: v = acc + xg,   cp = c[idx].
    const int evn = (lane & 1) == 0;   // q even: holds (i,f); q odd: (g,o)
    #pragma unroll
    for (int mb = 0; mb < 2; mb++) {
        const int r0 = bm + wy * 32 + mb * 16 + g;
        #pragma unroll
        for (int j = 0; j < 4; j++) {
            const int n0 = bn + wx * 32 + j * 8 + 2 * q;
            float v0, v1, v2, v3;
            if (gate_mode == 0) {
                const float d0 = bias[n0], d1 = bias[n0 + 1];
                v0 = acc[mb][j][0] + d0;
                v1 = acc[mb][j][1] + d1;
                v2 = acc[mb][j][2] + d0;
                v3 = acc[mb][j][3] + d1;
                *(float2*)(C + (size_t)r0 * G_ + n0)       = make_float2(v0, v1);
                *(float2*)(C + (size_t)(r0 + 8) * G_ + n0) = make_float2(v2, v3);
            } else {
                const float2 p0 = *(const float2*)(xg + (size_t)r0 * G_ + n0);
                const float2 p1 = *(const float2*)(xg + (size_t)(r0 + 8) * G_ + n0);
                v0 = acc[mb][j][0] + p0.x;
                v1 = acc[mb][j][1] + p0.y;
                v2 = acc[mb][j][2] + p1.x;
                v3 = acc[mb][j][3] + p1.y;
            }

            const float s0 = __shfl_xor_sync(0xffffffffu, v0, 1);
            const float s1 = __shfl_xor_sync(0xffffffffu, v1, 1);
            const float s2 = __shfl_xor_sync(0xffffffffu, v2, 1);
            const float s3 = __shfl_xor_sync(0xffffffffu, v3, 1);

            // even lane handles row r0; odd lane handles row r0+8
            const int   row = evn ? r0 : r0 + 8;
            const float gi = evn ? v0 : s2;
            const float gf = evn ? v1 : s3;
            const float gg = evn ? s0 : v2;
            const float go = evn ? s1 : v3;

            const float iv = 1.f / (1.f + expf(-gi));
            const float gv = tanhf(gg);
            const float ov = 1.f / (1.f + expf(-go));

            const int  u   = (n0 >> 2);               // original hidden unit
            const int  idx = row * H_ + u;
            float cn;
            if (gate_mode == 0) {
                cn = iv * gv;                          // c0 = 0
            } else {
                const float fv = 1.f / (1.f + expf(-gf));
                cn = fv * c[idx] + iv * gv;
            }
            c[idx] = cn;
            const float hv = ov * tanhf(cn);
            h_out[idx] = hv;
            const __nv_bfloat16 hb = __float2bfloat16(hv);
            hhi_out[idx] = hb;
            hlo_out[idx] = __float2bfloat16(hv - __bfloat162float(hb));
        }
    }
}

// ---------------------------------------------------------------------------
// Prep A (stream 0): wih decomp (gate-permuted) + x decomp + bias
// ---------------------------------------------------------------------------
#define NW (G_ * D_)
__global__ void prep_a(const float* __restrict__ x,
                       const float* __restrict__ Wih,
                       const float* __restrict__ bih,
                       const float* __restrict__ bhh,
                       __nv_bfloat16* __restrict__ wih_hi,
                       __nv_bfloat16* __restrict__ wih_lo,
                       __nv_bfloat16* __restrict__ x_hi,
                       __nv_bfloat16* __restrict__ x_lo,
                       float* __restrict__ bias)
{
    const long long i = (long long)blockIdx.x * blockDim.x + threadIdx.x;
    if (i < NW) {
        const int p   = (int)(i / D_);
        const int col = (int)(i - (long long)p * D_);
        const int srow = (p & 3) * H_ + (p >> 2);
        const float v = Wih[(size_t)srow * D_ + col];
        const __nv_bfloat16 hb = __float2bfloat16(v);
        wih_hi[i] = hb;
        wih_lo[i] = __float2bfloat16(v - __bfloat162float(hb));
    } else if (i < NW + B_ * D_) {
        const int j = (int)(i - NW);
        const float v = x[j];
        const __nv_bfloat16 hb = __float2bfloat16(v);
        x_hi[j] = hb;
        x_lo[j] = __float2bfloat16(v - __bfloat162float(hb));
    } else if (i < NW + B_ * D_ + G_) {
        const int p = (int)(i - NW - B_ * D_);
        const int o = (p & 3) * H_ + (p >> 2);
        bias[p] = bih[o] + bhh[o];
    }
}

// ---------------------------------------------------------------------------
// Prep B (side stream, overlapped with xg GEMM):
// whh decomp (gate-permuted) + wfe decomp (mu/sig-interleaved)
// ---------------------------------------------------------------------------
__global__ void prep_b(const float* __restrict__ Whh,
                       const float* __restrict__ Wfe,
                       __nv_bfloat16* __restrict__ whh_hi,
                       __nv_bfloat16* __restrict__ whh_lo,
                       __nv_bfloat16* __restrict__ wfe_hi,
                       __nv_bfloat16* __restrict__ wfe_lo)
{
    const long long i = (long long)blockIdx.x * blockDim.x + threadIdx.x;
    if (i < NW) {
        const int p   = (int)(i / H_);
        const int col = (int)(i - (long long)p * H_);
        const int srow = (p & 3) * H_ + (p >> 2);
        const float v = Whh[(size_t)srow * H_ + col];
        const __nv_bfloat16 hb = __float2bfloat16(v);
        whh_hi[i] = hb;
        whh_lo[i] = __float2bfloat16(v - __bfloat162float(hb));
    } else if (i < NW + 2LL * K_ * H_) {
        const int j   = (int)(i - NW);
        const int p   = j / H_;          // 0..127
        const int col = j - p * H_;
        const int srow = (p & 1) ? (K_ + (p >> 1)) : (p >> 1);   // mu/sig interleave
        const float v = Wfe[(size_t)srow * H_ + col];
        const __nv_bfloat16 hb = __float2bfloat16(v);
        wfe_hi[j] = hb;
        wfe_lo[j] = __float2bfloat16(v - __bfloat162float(hb));
    }
}

// ---------------------------------------------------------------------------
// Final-tick fe GEMM, split-K (fp32; runs once after the loop)
// ---------------------------------------------------------------------------
__global__ __launch_bounds__(256, 1)
void gemm_fe(const float* __restrict__ hmat,
             const float* __restrict__ Wfe,
             float* __restrict__ part)
{
    __shared__ float As[16][68];
    __shared__ float Bs[16][132];

    const int ks   = blockIdx.x;
    const int bm   = blockIdx.y * 64;
    const int koff = ks * KC;
    const int tid  = threadIdx.x;
    const int tx   = tid & 31;
    const int ty   = tid >> 5;

    float acc[8][4];
    #pragma unroll
    for (int i = 0; i < 8; i++)
        #pragma unroll
        for (int j = 0; j < 4; j++) acc[i][j] = 0.f;

    for (int k0 = 0; k0 < KC; k0 += 16) {
        {
            const int row = tid >> 2;
            const int c4  = (tid & 3) * 4;
            float4 v = *(const float4*)(hmat + (size_t)(bm + row) * H_ + koff + k0 + c4);
            As[c4 + 0][row] = v.x;  As[c4 + 1][row] = v.y;
            As[c4 + 2][row] = v.z;  As[c4 + 3][row] = v.w;
        }
        #pragma unroll
        for (int r = 0; r < 2; r++) {
            const int idx = tid + r * 256;
            const int rowb = idx >> 2;
            const int c4  = (idx & 3) * 4;
            float4 v = *(const float4*)(Wfe + (size_t)rowb * H_ + koff + k0 + c4);
            Bs[c4 + 0][rowb] = v.x;  Bs[c4 + 1][rowb] = v.y;
            Bs[c4 + 2][rowb] = v.z;  Bs[c4 + 3][rowb] = v.w;
        }
        __syncthreads();

        #pragma unroll
        for (int kk = 0; kk < 16; kk++) {
            float a[8], b[4];
            #pragma unroll
            for (int i = 0; i < 8; i++) a[i] = As[kk][ty + i * 8];
            #pragma unroll
            for (int j = 0; j < 4; j++) b[j] = Bs[kk][tx + j * 32];
            #pragma unroll
            for (int i = 0; i < 8; i++)
                #pragma unroll
                for (int j = 0; j < 4; j++)
                    acc[i][j] = fmaf(a[i], b[j], acc[i][j]);
        }
        __syncthreads();
    }

    #pragma unroll
    for (int i = 0; i < 8; i++) {
        const int m = bm + ty + i * 8;
        #pragma unroll
        for (int j = 0; j < 4; j++) {
            const int n = tx + j * 32;
            part[((size_t)ks * B_ + m) * (2 * K_) + n] = acc[i][j];
        }
    }
}

__global__ void z_kernel(const float* __restrict__ eps,
                         const float* __restrict__ bfe,
                         const float* __restrict__ part,
                         float* __restrict__ out,
                         int t)
{
    const int idx = blockIdx.x * blockDim.x + threadIdx.x;
    if (idx >= B_ * K_) return;
    const int b = idx / K_;
    const int k = idx - b * K_;

    float mu = bfe[k];
    float sr = bfe[k + K_];
    #pragma unroll 8
    for (int s = 0; s < NS; s++) {
        const float* p = part + ((size_t)s * B_ + b) * (2 * K_);
        mu += p[k];
        sr += p[k + K_];
    }

    const float xv  = sr - 5.f;
    const float sig = (xv > 20.f) ? xv : log1pf(expf(xv));
    const float e   = eps[((size_t)t * B_ + b) * K_ + k];
    const float z   = e * sig + mu;

    const size_t plane = (size_t)B_ * K_ * T_;
    const size_t o = ((size_t)b * K_ + k) * T_ + t;
    out[o]             = z;
    out[o + plane]     = mu;
    out[o + 2 * plane] = sig;
}

__global__ void hc_copy(const float* __restrict__ h,
                        const float* __restrict__ c,
                        float* __restrict__ out)
{
    const int idx = blockIdx.x * blockDim.x + threadIdx.x;
    if (idx >= B_ * H_) return;
    const size_t base = 3 * (size_t)B_ * K_ * T_;
    out[base + idx]           = h[idx];
    out[base + B_ * H_ + idx] = c[idx];
}

// ---------------------------------------------------------------------------
extern "C" void kernel_launch(void* const* d_in, const int* in_sizes, int n_in,
                              void* d_out, int out_size)
{
    const float* x   = (const float*)d_in[0];
    const float* eps = (const float*)d_in[1];
    const float* Wih = (const float*)d_in[2];
    const float* Whh = (const float*)d_in[3];
    const float* bih = (const float*)d_in[4];
    const float* bhh = (const float*)d_in[5];
    const float* Wfe = (const float*)d_in[6];
    const float* bfe = (const float*)d_in[7];
    float* out = (float*)d_out;

    __nv_bfloat16 *wih_hi, *wih_lo, *whh_hi, *whh_lo, *wfe_hi, *wfe_lo;
    __nv_bfloat16 *x_hi, *x_lo, *hhi2, *hlo2;
    float *xg, *h2, *c, *fep, *bias;
    cudaGetSymbolAddress((void**)&wih_hi, d_wih_hi);
    cudaGetSymbolAddress((void**)&wih_lo, d_wih_lo);
    cudaGetSymbolAddress((void**)&whh_hi, d_whh_hi);
    cudaGetSymbolAddress((void**)&whh_lo, d_whh_lo);
    cudaGetSymbolAddress((void**)&wfe_hi, d_wfe_hi);
    cudaGetSymbolAddress((void**)&wfe_lo, d_wfe_lo);
    cudaGetSymbolAddress((void**)&x_hi,   d_x_hi);
    cudaGetSymbolAddress((void**)&x_lo,   d_x_lo);
    cudaGetSymbolAddress((void**)&hhi2,   d_h_hi);
    cudaGetSymbolAddress((void**)&hlo2,   d_h_lo);
    cudaGetSymbolAddress((void**)&xg,   d_xg);
    cudaGetSymbolAddress((void**)&h2,   d_h);
    cudaGetSymbolAddress((void**)&c,    d_c);
    cudaGetSymbolAddress((void**)&fep,  d_fep);
    cudaGetSymbolAddress((void**)&bias, d_bias);

    __nv_bfloat16* hhi_buf[2] = { hhi2, hhi2 + B_ * H_ };
    __nv_bfloat16* hlo_buf[2] = { hlo2, hlo2 + B_ * H_ };
    float*         h_buf[2]   = { h2,   h2   + B_ * H_ };

    // One-time host resources (streams/events; created before graph capture)
    static cudaStream_t s2 = nullptr;
    static cudaEvent_t  evFork, evB;
    if (s2 == nullptr) {
        cudaStreamCreateWithFlags(&s2, cudaStreamNonBlocking);
        cudaEventCreateWithFlags(&evFork, cudaEventDisableTiming);
        cudaEventCreateWithFlags(&evB,    cudaEventDisableTiming);
        cudaFuncSetAttribute(gemm_mma2,
                             cudaFuncAttributeMaxDynamicSharedMemorySize,
                             SMEM_TOTAL);
    }

    const dim3 gTc0(G_ / 128, B_ / 64);    // (64, 4)  xg GEMM + t=0 cell update
    const dim3 gTc1(GA / 128, B_ / 64);    // (65, 4)  recurrent GEMM + fused fe
    const dim3 gFe(NS, B_ / 64);           // final-tick fe
    const int  eltBlocks = (B_ * H_ + 255) / 256;
    const int  zBlocks   = (B_ * K_ + 255) / 256;

    // Prep A on stream 0
    const long long prepAN = (long long)NW + B_ * D_ + G_;
    prep_a<<<(int)((prepAN + 255) / 256), 256>>>(
        x, Wih, bih, bhh, wih_hi, wih_lo, x_hi, x_lo, bias);

    // Capture-legal fork: record on origin stream, side stream waits, then runs
    cudaEventRecord(evFork, 0);
    cudaStreamWaitEvent(s2, evFork, 0);
    const long long prepBN = (long long)NW + 2LL * K_ * H_;
    prep_b<<<(int)((prepBN + 255) / 256), 256, 0, s2>>>(
        Whh, Wfe, whh_hi, whh_lo, wfe_hi, wfe_lo);
    cudaEventRecord(evB, s2);

    // xg GEMM + fused t=0 cell update (overlaps prep_b)
    gemm_mma2<<<gTc0, 256, SMEM_TOTAL>>>(x_hi, x_lo, wih_hi, wih_lo,
                                         nullptr, nullptr,
                                         nullptr, bias, xg,
                                         h_buf[0], c, hhi_buf[0], hlo_buf[0],
                                         nullptr, nullptr, nullptr, 0, 0);

    // Join: recurrent chain needs whh/wfe
    cudaStreamWaitEvent(0, evB, 0);

    for (int t = 1; t < T_; t++) {
        // GEMM(t): gates(t) from h(t-1)  +  fused fe/z for tick t-1
        gemm_mma2<<<gTc1, 256, SMEM_TOTAL>>>(
            hhi_buf[(t - 1) & 1], hlo_buf[(t - 1) & 1],
            whh_hi, whh_lo, wfe_hi, wfe_lo,
            xg, nullptr, nullptr,
            h_buf[t & 1], c, hhi_buf[t & 1], hlo_buf[t & 1],
            eps, bfe, out, t - 1, 1);
    }

    // Final tick's fe/z (t = T-1) + (h, c) copy
    gemm_fe<<<gFe, 256>>>(h_buf[(T_ - 1) & 1], Wfe, fep);
    z_kernel<<<zBlocks, 256>>>(eps, bfe, fep, out, T_ - 1);
    hc_copy<<<eltBlocks, 256>>>(h_buf[(T_ - 1) & 1], c, out);
}

// round 14
// speedup vs baseline: 1.5421x; 1.3329x over previous
#include <cuda_runtime.h>
#include <cuda_fp16.h>
#include <cstdint>
#include <math.h>

// Problem dims (fixed by setup_inputs)
#define B_ 256
#define D_ 2048
#define H_ 2048
#define K_ 64
#define T_ 32
#define G_ 8192           // 4*H
#define GA 8320           // augmented N: 4*H + 2*K (fused fe columns)
#define NS 64             // split-K factor for the final-tick fe GEMM
#define KC (H_ / NS)      // 32

// ---------------------------------------------------------------------------
// Scratch (device globals; no runtime allocation allowed)
// fp16 2-term split: X = xh + xl (exact to 2^-22), W single-rounded fp16.
// W_hh/W_ih rows GATE-INTERLEAVED: perm row p <- orig row (p&3)*H + (p>>2)
// W_fe rows MU/SIG-INTERLEAVED:    perm row p <- orig row (p&1)*K + (p>>1)
// h (fp32) and h hi/lo (fp16) PING-PONG buffered across ticks.
// ---------------------------------------------------------------------------
__device__ __half d_wih[G_ * D_];
__device__ __half d_whh[G_ * H_];
__device__ __half d_wfe[2 * K_ * H_];
__device__ __half d_x_hi[B_ * D_];
__device__ __half d_x_lo[B_ * D_];
__device__ __half d_h_hi[2][B_ * H_];
__device__ __half d_h_lo[2][B_ * H_];
__device__ float d_bias[G_];               // permuted b_ih + b_hh
__device__ float d_xg[B_ * G_];            // permuted cols
__device__ float d_h [2][B_ * H_];
__device__ float d_c [B_ * H_];
__device__ float d_fep[NS * B_ * 2 * K_];

__device__ __forceinline__ uint32_t smem_to_u32(const void* p) {
    uint32_t a;
    asm("{ .reg .u64 t; cvta.to.shared.u64 t, %1; cvt.u32.u64 %0, t; }"
        : "=r"(a) : "l"(p));
    return a;
}

// mma.sync m16n8k16 fp16 -> fp32 accumulate (plain sm_80+ PTX)
#define MMA16816(c, a0, a1, a2, a3, b0, b1) \
    asm volatile( \
        "mma.sync.aligned.m16n8k16.row.col.f32.f16.f16.f32 " \
        "{%0,%1,%2,%3}, {%4,%5,%6,%7}, {%8,%9}, {%0,%1,%2,%3};" \
        : "+f"((c)[0]), "+f"((c)[1]), "+f"((c)[2]), "+f"((c)[3]) \
        : "r"(a0), "r"(a1), "r"(a2), "r"(a3), "r"(b0), "r"(b1))

#define LDSM4(r, addr) \
    asm volatile("ldmatrix.sync.aligned.m8n8.x4.shared.b16 {%0,%1,%2,%3}, [%4];" \
        : "=r"((r)[0]), "=r"((r)[1]), "=r"((r)[2]), "=r"((r)[3]) : "r"(addr))

// ---------------------------------------------------------------------------
// Tensor-core fp16 2-term GEMM:  C = (Xhi + Xlo) * W   (fp32 accum)
// CTA tile 64m x 128n, BK=32, 8 warps (warp = 32m x 32n), 3-stage cp.async.
// 16 MMAs per warp per chunk (was 24 with bf16 3-term).
// gate_mode=0: grid (64,4): writes xg[m,n]=acc+bias AND does t=0 cell update
// gate_mode=1: grid (65,4): n-tiles 0..63: g = acc + xg -> fused LSTM update;
//              n-tile 64 (bn=G_): fused fe -> z/mu/sig for tick tprev.
// ---------------------------------------------------------------------------
#define BK     32
#define NCH    (D_ / BK)       // 64 chunks
#define ROWB   80              // padded row pitch (32 fp16 = 64B data + 16 pad)
#define TILEA  (64 * ROWB)     // 5120  (X tile: 64 rows)
#define TILEW  (128 * ROWB)    // 10240 (W tile: 128 rows)
#define OFF_XHI 0
#define OFF_W   (2 * TILEA)    // 10240
#define STAGEB  (2 * TILEA + TILEW)       // 20480
#define NSTAGE  3
#define SMEM_TOTAL (NSTAGE * STAGEB)      // 61440

__global__ __launch_bounds__(256, 2)
void gemm_mma2(const __half* __restrict__ Xhi,
               const __half* __restrict__ Xlo,
               const __half* __restrict__ W,
               const __half* __restrict__ F,     // wfe (gate_mode=1)
               const float* __restrict__ xg,     // gate_mode=1 (read)
               const float* __restrict__ bias,   // gate_mode=0
               float* __restrict__ C,            // gate_mode=0 (xg write)
               float* __restrict__ h_out,
               float* __restrict__ c,
               __half* __restrict__ hhi_out,
               __half* __restrict__ hlo_out,
               const float* __restrict__ eps,    // fused fe
               const float* __restrict__ bfe,    // fused fe
               float* __restrict__ zout,         // fused fe
               int tprev,                        // fused fe tick index
               int gate_mode)
{
    extern __shared__ __align__(16) char smem[];
    const uint32_t sm0 = smem_to_u32(smem);

    const int tid  = threadIdx.x;
    const int lane = tid & 31;
    const int w    = tid >> 5;
    const int wy   = w & 1;          // m sub-tile (2 x 32)
    const int wx   = w >> 1;         // n sub-tile (4 x 32)
    const int q    = lane & 3;
    const int g    = lane >> 2;
    const int bn   = blockIdx.x * 128;
    const int bm   = blockIdx.y * 64;
    const int feTile = (bn >= G_);

    // Hoisted cp.async addressing: 4 (global ptr, smem offset) pairs
    const __half* gsrc[4];
    uint32_t dofs[4];
    {
        const __half* xsrc[2] = { Xhi + (size_t)bm * D_, Xlo + (size_t)bm * D_ };
        const __half* wsrc = feTile ? F : W + (size_t)bn * D_;
        #pragma unroll
        for (int i = 0; i < 4; i++) {
            const int idx = i * 256 + tid;
            if (idx < 512) {
                const int v = idx >> 8, rem = idx & 255;
                const int row = rem >> 2, qu = rem & 3;
                dofs[i] = OFF_XHI + v * TILEA + row * ROWB + qu * 16;
                gsrc[i] = xsrc[v] + (size_t)row * D_ + qu * 8;
            } else {
                const int j = idx - 512;
                const int row = j >> 2, qu = j & 3;
                dofs[i] = OFF_W + row * ROWB + qu * 16;
                gsrc[i] = wsrc + (size_t)row * D_ + qu * 8;
            }
        }
    }

    // ldmatrix per-lane addressing
    const int lrow = (lane & 7) + ((lane >> 3) & 1) * 8;
    const int colh = (lane >> 4) * 16;

    float acc[2][4][4];
    #pragma unroll
    for (int a = 0; a < 2; a++)
        #pragma unroll
        for (int b = 0; b < 4; b++)
            #pragma unroll
            for (int d = 0; d < 4; d++) acc[a][b][d] = 0.f;

#define ISSUE(st) do {                                                        \
    const uint32_t _stb = sm0 + (st) * STAGEB;                                \
    _Pragma("unroll")                                                         \
    for (int i = 0; i < 4; i++) {                                             \
        asm volatile("cp.async.cg.shared.global [%0], [%1], 16;"              \
                     :: "r"(_stb + dofs[i]), "l"(gsrc[i]));                   \
        gsrc[i] += BK;                                                        \
    }                                                                         \
    asm volatile("cp.async.commit_group;" ::: "memory");                      \
} while (0)

    ISSUE(0);
    ISSUE(1);

    int st = 0, st_issue = 2;
    for (int ch = 0; ch < NCH; ch++) {
        if (ch < NCH - 1) asm volatile("cp.async.wait_group 1;" ::: "memory");
        else              asm volatile("cp.async.wait_group 0;" ::: "memory");
        __syncthreads();
        if (ch + 2 < NCH) {
            ISSUE(st_issue);
            st_issue = st_issue + 1 >= NSTAGE ? 0 : st_issue + 1;
        }

        const uint32_t stb = sm0 + st * STAGEB;
        const uint32_t aHi = stb + OFF_XHI + (wy * 32 + lrow) * ROWB + colh;
        const uint32_t bBs = stb + OFF_W + (wx * 32 + lrow) * ROWB + colh;

        #pragma unroll
        for (int ks = 0; ks < 2; ks++) {
            uint32_t ah[2][4], al[2][4], bh[2][4];
            #pragma unroll
            for (int mb = 0; mb < 2; mb++) {
                LDSM4(ah[mb], aHi + mb * 16 * ROWB + ks * 32);
                LDSM4(al[mb], aHi + TILEA + mb * 16 * ROWB + ks * 32);
            }
            #pragma unroll
            for (int t2 = 0; t2 < 2; t2++)
                LDSM4(bh[t2], bBs + t2 * 16 * ROWB + ks * 32);

            // Term-major issue: 8 independent MMAs per term, 2 terms
            #pragma unroll
            for (int t2 = 0; t2 < 2; t2++)
                #pragma unroll
                for (int mb = 0; mb < 2; mb++) {
                    MMA16816(acc[mb][t2 * 2],     ah[mb][0], ah[mb][1], ah[mb][2], ah[mb][3], bh[t2][0], bh[t2][2]);
                    MMA16816(acc[mb][t2 * 2 + 1], ah[mb][0], ah[mb][1], ah[mb][2], ah[mb][3], bh[t2][1], bh[t2][3]);
                }
            #pragma unroll
            for (int t2 = 0; t2 < 2; t2++)
                #pragma unroll
                for (int mb = 0; mb < 2; mb++) {
                    MMA16816(acc[mb][t2 * 2],     al[mb][0], al[mb][1], al[mb][2], al[mb][3], bh[t2][0], bh[t2][2]);
                    MMA16816(acc[mb][t2 * 2 + 1], al[mb][0], al[mb][1], al[mb][2], al[mb][3], bh[t2][1], bh[t2][3]);
                }
        }
        st = st + 1 >= NSTAGE ? 0 : st + 1;
        // next iteration's __syncthreads protects stage reuse
    }
#undef ISSUE

    // ---------------- Epilogues ----------------
    if (gate_mode == 1 && feTile) {
        // Fused fe/z epilogue: cols (2k, 2k+1) = (mu_k partial, sig_k partial)
        const size_t plane = (size_t)B_ * K_ * T_;
        #pragma unroll
        for (int mb = 0; mb < 2; mb++) {
            const int r0 = bm + wy * 32 + mb * 16 + g;
            #pragma unroll
            for (int j = 0; j < 4; j++) {
                const int col = wx * 32 + j * 8 + 2 * q;   // 0..127, even
                const int k   = col >> 1;
                const float bmu = bfe[k];
                const float bsr = bfe[K_ + k];
                #pragma unroll
                for (int rr = 0; rr < 2; rr++) {
                    const int   b  = r0 + rr * 8;
                    const float mu = acc[mb][j][rr * 2 + 0] + bmu;
                    const float xv = acc[mb][j][rr * 2 + 1] + bsr - 5.f;
                    const float sig = (xv > 20.f) ? xv : log1pf(expf(xv));
                    const float e  = eps[((size_t)tprev * B_ + b) * K_ + k];
                    const size_t o = ((size_t)b * K_ + k) * T_ + tprev;
                    zout[o]             = e * sig + mu;
                    zout[o + plane]     = mu;
                    zout[o + 2 * plane] = sig;
                }
            }
        }
        return;
    }

    // Gate epilogue (both modes). mode 0: v = acc + bias, write xg, cp = 0.
    //                             mode 1: v = acc + xg,   cp = c[idx].
    const int evn = (lane & 1) == 0;   // q even: holds (i,f); q odd: (g,o)
    #pragma unroll
    for (int mb = 0; mb < 2; mb++) {
        const int r0 = bm + wy * 32 + mb * 16 + g;
        #pragma unroll
        for (int j = 0; j < 4; j++) {
            const int n0 = bn + wx * 32 + j * 8 + 2 * q;
            float v0, v1, v2, v3;
            if (gate_mode == 0) {
                const float d0 = bias[n0], d1 = bias[n0 + 1];
                v0 = acc[mb][j][0] + d0;
                v1 = acc[mb][j][1] + d1;
                v2 = acc[mb][j][2] + d0;
                v3 = acc[mb][j][3] + d1;
                *(float2*)(C + (size_t)r0 * G_ + n0)       = make_float2(v0, v1);
                *(float2*)(C + (size_t)(r0 + 8) * G_ + n0) = make_float2(v2, v3);
            } else {
                const float2 p0 = *(const float2*)(xg + (size_t)r0 * G_ + n0);
                const float2 p1 = *(const float2*)(xg + (size_t)(r0 + 8) * G_ + n0);
                v0 = acc[mb][j][0] + p0.x;
                v1 = acc[mb][j][1] + p0.y;
                v2 = acc[mb][j][2] + p1.x;
                v3 = acc[mb][j][3] + p1.y;
            }

            const float s0 = __shfl_xor_sync(0xffffffffu, v0, 1);
            const float s1 = __shfl_xor_sync(0xffffffffu, v1, 1);
            const float s2 = __shfl_xor_sync(0xffffffffu, v2, 1);
            const float s3 = __shfl_xor_sync(0xffffffffu, v3, 1);

            // even lane handles row r0; odd lane handles row r0+8
            const int   row = evn ? r0 : r0 + 8;
            const float gi = evn ? v0 : s2;
            const float gf = evn ? v1 : s3;
            const float gg = evn ? s0 : v2;
            const float go = evn ? s1 : v3;

            const float iv = 1.f / (1.f + expf(-gi));
            const float gv = tanhf(gg);
            const float ov = 1.f / (1.f + expf(-go));

            const int  u   = (n0 >> 2);               // original hidden unit
            const int  idx = row * H_ + u;
            float cn;
            if (gate_mode == 0) {
                cn = iv * gv;                          // c0 = 0
            } else {
                const float fv = 1.f / (1.f + expf(-gf));
                cn = fv * c[idx] + iv * gv;
            }
            c[idx] = cn;
            const float hv = ov * tanhf(cn);
            h_out[idx] = hv;
            const __half hb = __float2half(hv);
            hhi_out[idx] = hb;
            hlo_out[idx] = __float2half(hv - __half2float(hb));
        }
    }
}

// ---------------------------------------------------------------------------
// Prep A (stream 0): wih -> fp16 (gate-permuted) + x hi/lo split + bias
// ---------------------------------------------------------------------------
#define NW (G_ * D_)
__global__ void prep_a(const float* __restrict__ x,
                       const float* __restrict__ Wih,
                       const float* __restrict__ bih,
                       const float* __restrict__ bhh,
                       __half* __restrict__ wih,
                       __half* __restrict__ x_hi,
                       __half* __restrict__ x_lo,
                       float* __restrict__ bias)
{
    const long long i = (long long)blockIdx.x * blockDim.x + threadIdx.x;
    if (i < NW) {
        const int p   = (int)(i / D_);
        const int col = (int)(i - (long long)p * D_);
        const int srow = (p & 3) * H_ + (p >> 2);
        wih[i] = __float2half(Wih[(size_t)srow * D_ + col]);
    } else if (i < NW + B_ * D_) {
        const int j = (int)(i - NW);
        const float v = x[j];
        const __half hb = __float2half(v);
        x_hi[j] = hb;
        x_lo[j] = __float2half(v - __half2float(hb));
    } else if (i < NW + B_ * D_ + G_) {
        const int p = (int)(i - NW - B_ * D_);
        const int o = (p & 3) * H_ + (p >> 2);
        bias[p] = bih[o] + bhh[o];
    }
}

// ---------------------------------------------------------------------------
// Prep B (side stream, overlapped with xg GEMM):
// whh -> fp16 (gate-permuted) + wfe -> fp16 (mu/sig-interleaved)
// ---------------------------------------------------------------------------
__global__ void prep_b(const float* __restrict__ Whh,
                       const float* __restrict__ Wfe,
                       __half* __restrict__ whh,
                       __half* __restrict__ wfe)
{
    const long long i = (long long)blockIdx.x * blockDim.x + threadIdx.x;
    if (i < NW) {
        const int p   = (int)(i / H_);
        const int col = (int)(i - (long long)p * H_);
        const int srow = (p & 3) * H_ + (p >> 2);
        whh[i] = __float2half(Whh[(size_t)srow * H_ + col]);
    } else if (i < NW + 2LL * K_ * H_) {
        const int j   = (int)(i - NW);
        const int p   = j / H_;          // 0..127
        const int col = j - p * H_;
        const int srow = (p & 1) ? (K_ + (p >> 1)) : (p >> 1);   // mu/sig interleave
        wfe[j] = __float2half(Wfe[(size_t)srow * H_ + col]);
    }
}

// ---------------------------------------------------------------------------
// Final-tick fe GEMM, split-K (fp32; runs once after the loop)
// ---------------------------------------------------------------------------
__global__ __launch_bounds__(256, 1)
void gemm_fe(const float* __restrict__ hmat,
             const float* __restrict__ Wfe,
             float* __restrict__ part)
{
    __shared__ float As[16][68];
    __shared__ float Bs[16][132];

    const int ks   = blockIdx.x;
    const int bm   = blockIdx.y * 64;
    const int koff = ks * KC;
    const int tid  = threadIdx.x;
    const int tx   = tid & 31;
    const int ty   = tid >> 5;

    float acc[8][4];
    #pragma unroll
    for (int i = 0; i < 8; i++)
        #pragma unroll
        for (int j = 0; j < 4; j++) acc[i][j] = 0.f;

    for (int k0 = 0; k0 < KC; k0 += 16) {
        {
            const int row = tid >> 2;
            const int c4  = (tid & 3) * 4;
            float4 v = *(const float4*)(hmat + (size_t)(bm + row) * H_ + koff + k0 + c4);
            As[c4 + 0][row] = v.x;  As[c4 + 1][row] = v.y;
            As[c4 + 2][row] = v.z;  As[c4 + 3][row] = v.w;
        }
        #pragma unroll
        for (int r = 0; r < 2; r++) {
            const int idx = tid + r * 256;
            const int rowb = idx >> 2;
            const int c4  = (idx & 3) * 4;
            float4 v = *(const float4*)(Wfe + (size_t)rowb * H_ + koff + k0 + c4);
            Bs[c4 + 0][rowb] = v.x;  Bs[c4 + 1][rowb] = v.y;
            Bs[c4 + 2][rowb] = v.z;  Bs[c4 + 3][rowb] = v.w;
        }
        __syncthreads();

        #pragma unroll
        for (int kk = 0; kk < 16; kk++) {
            float a[8], b[4];
            #pragma unroll
            for (int i = 0; i < 8; i++) a[i] = As[kk][ty + i * 8];
            #pragma unroll
            for (int j = 0; j < 4; j++) b[j] = Bs[kk][tx + j * 32];
            #pragma unroll
            for (int i = 0; i < 8; i++)
                #pragma unroll
                for (int j = 0; j < 4; j++)
                    acc[i][j] = fmaf(a[i], b[j], acc[i][j]);
        }
        __syncthreads();
    }

    #pragma unroll
    for (int i = 0; i < 8; i++) {
        const int m = bm + ty + i * 8;
        #pragma unroll
        for (int j = 0; j < 4; j++) {
            const int n = tx + j * 32;
            part[((size_t)ks * B_ + m) * (2 * K_) + n] = acc[i][j];
        }
    }
}

__global__ void z_kernel(const float* __restrict__ eps,
                         const float* __restrict__ bfe,
                         const float* __restrict__ part,
                         float* __restrict__ out,
                         int t)
{
    const int idx = blockIdx.x * blockDim.x + threadIdx.x;
    if (idx >= B_ * K_) return;
    const int b = idx / K_;
    const int k = idx - b * K_;

    float mu = bfe[k];
    float sr = bfe[k + K_];
    #pragma unroll 8
    for (int s = 0; s < NS; s++) {
        const float* p = part + ((size_t)s * B_ + b) * (2 * K_);
        mu += p[k];
        sr += p[k + K_];
    }

    const float xv  = sr - 5.f;
    const float sig = (xv > 20.f) ? xv : log1pf(expf(xv));
    const float e   = eps[((size_t)t * B_ + b) * K_ + k];
    const float z   = e * sig + mu;

    const size_t plane = (size_t)B_ * K_ * T_;
    const size_t o = ((size_t)b * K_ + k) * T_ + t;
    out[o]             = z;
    out[o + plane]     = mu;
    out[o + 2 * plane] = sig;
}

__global__ void hc_copy(const float* __restrict__ h,
                        const float* __restrict__ c,
                        float* __restrict__ out)
{
    const int idx = blockIdx.x * blockDim.x + threadIdx.x;
    if (idx >= B_ * H_) return;
    const size_t base = 3 * (size_t)B_ * K_ * T_;
    out[base + idx]           = h[idx];
    out[base + B_ * H_ + idx] = c[idx];
}

// ---------------------------------------------------------------------------
extern "C" void kernel_launch(void* const* d_in, const int* in_sizes, int n_in,
                              void* d_out, int out_size)
{
    const float* x   = (const float*)d_in[0];
    const float* eps = (const float*)d_in[1];
    const float* Wih = (const float*)d_in[2];
    const float* Whh = (const float*)d_in[3];
    const float* bih = (const float*)d_in[4];
    const float* bhh = (const float*)d_in[5];
    const float* Wfe = (const float*)d_in[6];
    const float* bfe = (const float*)d_in[7];
    float* out = (float*)d_out;

    __half *wih, *whh, *wfe, *x_hi, *x_lo, *hhi2, *hlo2;
    float *xg, *h2, *c, *fep, *bias;
    cudaGetSymbolAddress((void**)&wih,  d_wih);
    cudaGetSymbolAddress((void**)&whh,  d_whh);
    cudaGetSymbolAddress((void**)&wfe,  d_wfe);
    cudaGetSymbolAddress((void**)&x_hi, d_x_hi);
    cudaGetSymbolAddress((void**)&x_lo, d_x_lo);
    cudaGetSymbolAddress((void**)&hhi2, d_h_hi);
    cudaGetSymbolAddress((void**)&hlo2, d_h_lo);
    cudaGetSymbolAddress((void**)&xg,   d_xg);
    cudaGetSymbolAddress((void**)&h2,   d_h);
    cudaGetSymbolAddress((void**)&c,    d_c);
    cudaGetSymbolAddress((void**)&fep,  d_fep);
    cudaGetSymbolAddress((void**)&bias, d_bias);

    __half* hhi_buf[2] = { hhi2, hhi2 + B_ * H_ };
    __half* hlo_buf[2] = { hlo2, hlo2 + B_ * H_ };
    float*  h_buf[2]   = { h2,   h2   + B_ * H_ };

    // One-time host resources (streams/events; created before graph capture)
    static cudaStream_t s2 = nullptr;
    static cudaEvent_t  evFork, evB;
    if (s2 == nullptr) {
        cudaStreamCreateWithFlags(&s2, cudaStreamNonBlocking);
        cudaEventCreateWithFlags(&evFork, cudaEventDisableTiming);
        cudaEventCreateWithFlags(&evB,    cudaEventDisableTiming);
        cudaFuncSetAttribute(gemm_mma2,
                             cudaFuncAttributeMaxDynamicSharedMemorySize,
                             SMEM_TOTAL);
    }

    const dim3 gTc0(G_ / 128, B_ / 64);    // (64, 4)  xg GEMM + t=0 cell update
    const dim3 gTc1(GA / 128, B_ / 64);    // (65, 4)  recurrent GEMM + fused fe
    const dim3 gFe(NS, B_ / 64);           // final-tick fe
    const int  eltBlocks = (B_ * H_ + 255) / 256;
    const int  zBlocks   = (B_ * K_ + 255) / 256;

    // Prep A on stream 0
    const long long prepAN = (long long)NW + B_ * D_ + G_;
    prep_a<<<(int)((prepAN + 255) / 256), 256>>>(
        x, Wih, bih, bhh, wih, x_hi, x_lo, bias);

    // Capture-legal fork: record on origin stream, side stream waits, then runs
    cudaEventRecord(evFork, 0);
    cudaStreamWaitEvent(s2, evFork, 0);
    const long long prepBN = (long long)NW + 2LL * K_ * H_;
    prep_b<<<(int)((prepBN + 255) / 256), 256, 0, s2>>>(Whh, Wfe, whh, wfe);
    cudaEventRecord(evB, s2);

    // xg GEMM + fused t=0 cell update (overlaps prep_b)
    gemm_mma2<<<gTc0, 256, SMEM_TOTAL>>>(x_hi, x_lo, wih, nullptr,
                                         nullptr, bias, xg,
                                         h_buf[0], c, hhi_buf[0], hlo_buf[0],
                                         nullptr, nullptr, nullptr, 0, 0);

    // Join: recurrent chain needs whh/wfe
    cudaStreamWaitEvent(0, evB, 0);

    for (int t = 1; t < T_; t++) {
        // GEMM(t): gates(t) from h(t-1)  +  fused fe/z for tick t-1
        gemm_mma2<<<gTc1, 256, SMEM_TOTAL>>>(
            hhi_buf[(t - 1) & 1], hlo_buf[(t - 1) & 1],
            whh, wfe,
            xg, nullptr, nullptr,
            h_buf[t & 1], c, hhi_buf[t & 1], hlo_buf[t & 1],
            eps, bfe, out, t - 1, 1);
    }

    // Final tick's fe/z (t = T-1) + (h, c) copy
    gemm_fe<<<gFe, 256>>>(h_buf[(T_ - 1) & 1], Wfe, fep);
    z_kernel<<<zBlocks, 256>>>(eps, bfe, fep, out, T_ - 1);
    hc_copy<<<eltBlocks, 256>>>(h_buf[(T_ - 1) & 1], c, out);
}

// round 15
// speedup vs baseline: 2.4072x; 1.5610x over previous
#include <cuda_runtime.h>
#include <cuda_fp16.h>
#include <cstdint>
#include <math.h>

// Problem dims (fixed by setup_inputs)
#define B_ 256
#define D_ 2048
#define H_ 2048
#define K_ 64
#define T_ 32
#define G_ 8192           // 4*H
#define GA 8320           // augmented N: 4*H + 2*K (fused fe columns)
#define NS 64             // split-K factor for the final-tick fe GEMM
#define KC (H_ / NS)      // 32

// ---------------------------------------------------------------------------
// Scratch (device globals; no runtime allocation allowed)
// Single-term fp16: both X and W rounded to fp16, fp32 accumulate.
// W_hh/W_ih rows GATE-INTERLEAVED: perm row p <- orig row (p&3)*H + (p>>2)
// W_fe rows MU/SIG-INTERLEAVED:    perm row p <- orig row (p&1)*K + (p>>1)
// h (fp32) and h (fp16) PING-PONG buffered across ticks.
// ---------------------------------------------------------------------------
__device__ __half d_wih[G_ * D_];
__device__ __half d_whh[G_ * H_];
__device__ __half d_wfe[2 * K_ * H_];
__device__ __half d_x16[B_ * D_];
__device__ __half d_h16[2][B_ * H_];
__device__ float d_bias[G_];               // permuted b_ih + b_hh
__device__ float d_xg[B_ * G_];            // permuted cols
__device__ float d_h [2][B_ * H_];
__device__ float d_c [B_ * H_];
__device__ float d_fep[NS * B_ * 2 * K_];

__device__ __forceinline__ uint32_t smem_to_u32(const void* p) {
    uint32_t a;
    asm("{ .reg .u64 t; cvta.to.shared.u64 t, %1; cvt.u32.u64 %0, t; }"
        : "=r"(a) : "l"(p));
    return a;
}

// mma.sync m16n8k16 fp16 -> fp32 accumulate (plain sm_80+ PTX)
#define MMA16816(c, a0, a1, a2, a3, b0, b1) \
    asm volatile( \
        "mma.sync.aligned.m16n8k16.row.col.f32.f16.f16.f32 " \
        "{%0,%1,%2,%3}, {%4,%5,%6,%7}, {%8,%9}, {%0,%1,%2,%3};" \
        : "+f"((c)[0]), "+f"((c)[1]), "+f"((c)[2]), "+f"((c)[3]) \
        : "r"(a0), "r"(a1), "r"(a2), "r"(a3), "r"(b0), "r"(b1))

#define LDSM4(r, addr) \
    asm volatile("ldmatrix.sync.aligned.m8n8.x4.shared.b16 {%0,%1,%2,%3}, [%4];" \
        : "=r"((r)[0]), "=r"((r)[1]), "=r"((r)[2]), "=r"((r)[3]) : "r"(addr))

// ---------------------------------------------------------------------------
// Tensor-core fp16 single-term GEMM:  C = X * W   (fp32 accum)
// CTA tile 64m x 128n, BK=32, 8 warps (warp = 32m x 32n), 3-stage cp.async.
// 8 MMAs per warp per k16 step (16 per chunk).
// gate_mode=0: grid (64,4): writes xg[m,n]=acc+bias AND does t=0 cell update
// gate_mode=1: grid (65,4): n-tiles 0..63: g = acc + xg -> fused LSTM update;
//              n-tile 64 (bn=G_): fused fe -> z/mu/sig for tick tprev.
// ---------------------------------------------------------------------------
#define BK     32
#define NCH    (D_ / BK)       // 64 chunks
#define ROWB   80              // padded row pitch (32 fp16 = 64B data + 16 pad)
#define TILEA  (64 * ROWB)     // 5120  (X tile: 64 rows)
#define TILEW  (128 * ROWB)    // 10240 (W tile: 128 rows)
#define OFF_X  0
#define OFF_W  TILEA           // 5120
#define STAGEB (TILEA + TILEW) // 15360
#define NSTAGE 3
#define SMEM_TOTAL (NSTAGE * STAGEB)      // 46080

__global__ __launch_bounds__(256, 2)
void gemm_mma2(const __half* __restrict__ X,
               const __half* __restrict__ W,
               const __half* __restrict__ F,     // wfe (gate_mode=1)
               const float* __restrict__ xg,     // gate_mode=1 (read)
               const float* __restrict__ bias,   // gate_mode=0
               float* __restrict__ C,            // gate_mode=0 (xg write)
               float* __restrict__ h_out,
               float* __restrict__ c,
               __half* __restrict__ h16_out,
               const float* __restrict__ eps,    // fused fe
               const float* __restrict__ bfe,    // fused fe
               float* __restrict__ zout,         // fused fe
               int tprev,                        // fused fe tick index
               int gate_mode)
{
    extern __shared__ __align__(16) char smem[];
    const uint32_t sm0 = smem_to_u32(smem);

    const int tid  = threadIdx.x;
    const int lane = tid & 31;
    const int w    = tid >> 5;
    const int wy   = w & 1;          // m sub-tile (2 x 32)
    const int wx   = w >> 1;         // n sub-tile (4 x 32)
    const int q    = lane & 3;
    const int g    = lane >> 2;
    const int bn   = blockIdx.x * 128;
    const int bm   = blockIdx.y * 64;
    const int feTile = (bn >= G_);

    // Hoisted cp.async addressing: 3 (global ptr, smem offset) pairs
    // 768 16B-loads per stage: [0,256) X tile, [256,768) W tile
    const __half* gsrc[3];
    uint32_t dofs[3];
    {
        const __half* xs = X + (size_t)bm * D_;
        const __half* ws = feTile ? F : W + (size_t)bn * D_;
        #pragma unroll
        for (int i = 0; i < 3; i++) {
            const int idx = i * 256 + tid;
            if (idx < 256) {
                const int row = idx >> 2, qu = idx & 3;
                dofs[i] = OFF_X + row * ROWB + qu * 16;
                gsrc[i] = xs + (size_t)row * D_ + qu * 8;
            } else {
                const int j = idx - 256;
                const int row = j >> 2, qu = j & 3;
                dofs[i] = OFF_W + row * ROWB + qu * 16;
                gsrc[i] = ws + (size_t)row * D_ + qu * 8;
            }
        }
    }

    // ldmatrix per-lane addressing
    const int lrow = (lane & 7) + ((lane >> 3) & 1) * 8;
    const int colh = (lane >> 4) * 16;

    float acc[2][4][4];
    #pragma unroll
    for (int a = 0; a < 2; a++)
        #pragma unroll
        for (int b = 0; b < 4; b++)
            #pragma unroll
            for (int d = 0; d < 4; d++) acc[a][b][d] = 0.f;

#define ISSUE(st) do {                                                        \
    const uint32_t _stb = sm0 + (st) * STAGEB;                                \
    _Pragma("unroll")                                                         \
    for (int i = 0; i < 3; i++) {                                             \
        asm volatile("cp.async.cg.shared.global [%0], [%1], 16;"              \
                     :: "r"(_stb + dofs[i]), "l"(gsrc[i]));                   \
        gsrc[i] += BK;                                                        \
    }                                                                         \
    asm volatile("cp.async.commit_group;" ::: "memory");                      \
} while (0)

    ISSUE(0);
    ISSUE(1);

    int st = 0, st_issue = 2;
    for (int ch = 0; ch < NCH; ch++) {
        if (ch < NCH - 1) asm volatile("cp.async.wait_group 1;" ::: "memory");
        else              asm volatile("cp.async.wait_group 0;" ::: "memory");
        __syncthreads();
        if (ch + 2 < NCH) {
            ISSUE(st_issue);
            st_issue = st_issue + 1 >= NSTAGE ? 0 : st_issue + 1;
        }

        const uint32_t stb = sm0 + st * STAGEB;
        const uint32_t aBs = stb + OFF_X + (wy * 32 + lrow) * ROWB + colh;
        const uint32_t bBs = stb + OFF_W + (wx * 32 + lrow) * ROWB + colh;

        #pragma unroll
        for (int ks = 0; ks < 2; ks++) {
            uint32_t ah[2][4], bh[2][4];
            #pragma unroll
            for (int mb = 0; mb < 2; mb++)
                LDSM4(ah[mb], aBs + mb * 16 * ROWB + ks * 32);
            #pragma unroll
            for (int t2 = 0; t2 < 2; t2++)
                LDSM4(bh[t2], bBs + t2 * 16 * ROWB + ks * 32);

            #pragma unroll
            for (int t2 = 0; t2 < 2; t2++)
                #pragma unroll
                for (int mb = 0; mb < 2; mb++) {
                    MMA16816(acc[mb][t2 * 2],     ah[mb][0], ah[mb][1], ah[mb][2], ah[mb][3], bh[t2][0], bh[t2][2]);
                    MMA16816(acc[mb][t2 * 2 + 1], ah[mb][0], ah[mb][1], ah[mb][2], ah[mb][3], bh[t2][1], bh[t2][3]);
                }
        }
        st = st + 1 >= NSTAGE ? 0 : st + 1;
        // next iteration's __syncthreads protects stage reuse
    }
#undef ISSUE

    // ---------------- Epilogues ----------------
    if (gate_mode == 1 && feTile) {
        // Fused fe/z epilogue: cols (2k, 2k+1) = (mu_k partial, sig_k partial)
        const size_t plane = (size_t)B_ * K_ * T_;
        #pragma unroll
        for (int mb = 0; mb < 2; mb++) {
            const int r0 = bm + wy * 32 + mb * 16 + g;
            #pragma unroll
            for (int j = 0; j < 4; j++) {
                const int col = wx * 32 + j * 8 + 2 * q;   // 0..127, even
                const int k   = col >> 1;
                const float bmu = bfe[k];
                const float bsr = bfe[K_ + k];
                #pragma unroll
                for (int rr = 0; rr < 2; rr++) {
                    const int   b  = r0 + rr * 8;
                    const float mu = acc[mb][j][rr * 2 + 0] + bmu;
                    const float xv = acc[mb][j][rr * 2 + 1] + bsr - 5.f;
                    const float sig = (xv > 20.f) ? xv : log1pf(expf(xv));
                    const float e  = eps[((size_t)tprev * B_ + b) * K_ + k];
                    const size_t o = ((size_t)b * K_ + k) * T_ + tprev;
                    zout[o]             = e * sig + mu;
                    zout[o + plane]     = mu;
                    zout[o + 2 * plane] = sig;
                }
            }
        }
        return;
    }

    // Gate epilogue (both modes). mode 0: v = acc + bias, write xg, cp = 0.
    //                             mode 1: v = acc + xg,   cp = c[idx].
    const int evn = (lane & 1) == 0;   // q even: holds (i,f); q odd: (g,o)
    #pragma unroll
    for (int mb = 0; mb < 2; mb++) {
        const int r0 = bm + wy * 32 + mb * 16 + g;
        #pragma unroll
        for (int j = 0; j < 4; j++) {
            const int n0 = bn + wx * 32 + j * 8 + 2 * q;
            float v0, v1, v2, v3;
            if (gate_mode == 0) {
                const float d0 = bias[n0], d1 = bias[n0 + 1];
                v0 = acc[mb][j][0] + d0;
                v1 = acc[mb][j][1] + d1;
                v2 = acc[mb][j][2] + d0;
                v3 = acc[mb][j][3] + d1;
                *(float2*)(C + (size_t)r0 * G_ + n0)       = make_float2(v0, v1);
                *(float2*)(C + (size_t)(r0 + 8) * G_ + n0) = make_float2(v2, v3);
            } else {
                const float2 p0 = *(const float2*)(xg + (size_t)r0 * G_ + n0);
                const float2 p1 = *(const float2*)(xg + (size_t)(r0 + 8) * G_ + n0);
                v0 = acc[mb][j][0] + p0.x;
                v1 = acc[mb][j][1] + p0.y;
                v2 = acc[mb][j][2] + p1.x;
                v3 = acc[mb][j][3] + p1.y;
            }

            const float s0 = __shfl_xor_sync(0xffffffffu, v0, 1);
            const float s1 = __shfl_xor_sync(0xffffffffu, v1, 1);
            const float s2 = __shfl_xor_sync(0xffffffffu, v2, 1);
            const float s3 = __shfl_xor_sync(0xffffffffu, v3, 1);

            // even lane handles row r0; odd lane handles row r0+8
            const int   row = evn ? r0 : r0 + 8;
            const float gi = evn ? v0 : s2;
            const float gf = evn ? v1 : s3;
            const float gg = evn ? s0 : v2;
            const float go = evn ? s1 : v3;

            const float iv = 1.f / (1.f + expf(-gi));
            const float gv = tanhf(gg);
            const float ov = 1.f / (1.f + expf(-go));

            const int  u   = (n0 >> 2);               // original hidden unit
            const int  idx = row * H_ + u;
            float cn;
            if (gate_mode == 0) {
                cn = iv * gv;                          // c0 = 0
            } else {
                const float fv = 1.f / (1.f + expf(-gf));
                cn = fv * c[idx] + iv * gv;
            }
            c[idx] = cn;
            const float hv = ov * tanhf(cn);
            h_out[idx] = hv;
            h16_out[idx] = __float2half(hv);
        }
    }
}

// ---------------------------------------------------------------------------
// Prep A (stream 0): wih -> fp16 (gate-permuted) + x -> fp16 + bias
// ---------------------------------------------------------------------------
#define NW (G_ * D_)
__global__ void prep_a(const float* __restrict__ x,
                       const float* __restrict__ Wih,
                       const float* __restrict__ bih,
                       const float* __restrict__ bhh,
                       __half* __restrict__ wih,
                       __half* __restrict__ x16,
                       float* __restrict__ bias)
{
    const long long i = (long long)blockIdx.x * blockDim.x + threadIdx.x;
    if (i < NW) {
        const int p   = (int)(i / D_);
        const int col = (int)(i - (long long)p * D_);
        const int srow = (p & 3) * H_ + (p >> 2);
        wih[i] = __float2half(Wih[(size_t)srow * D_ + col]);
    } else if (i < NW + B_ * D_) {
        const int j = (int)(i - NW);
        x16[j] = __float2half(x[j]);
    } else if (i < NW + B_ * D_ + G_) {
        const int p = (int)(i - NW - B_ * D_);
        const int o = (p & 3) * H_ + (p >> 2);
        bias[p] = bih[o] + bhh[o];
    }
}

// ---------------------------------------------------------------------------
// Prep B (side stream, overlapped with xg GEMM):
// whh -> fp16 (gate-permuted) + wfe -> fp16 (mu/sig-interleaved)
// ---------------------------------------------------------------------------
__global__ void prep_b(const float* __restrict__ Whh,
                       const float* __restrict__ Wfe,
                       __half* __restrict__ whh,
                       __half* __restrict__ wfe)
{
    const long long i = (long long)blockIdx.x * blockDim.x + threadIdx.x;
    if (i < NW) {
        const int p   = (int)(i / H_);
        const int col = (int)(i - (long long)p * H_);
        const int srow = (p & 3) * H_ + (p >> 2);
        whh[i] = __float2half(Whh[(size_t)srow * H_ + col]);
    } else if (i < NW + 2LL * K_ * H_) {
        const int j   = (int)(i - NW);
        const int p   = j / H_;          // 0..127
        const int col = j - p * H_;
        const int srow = (p & 1) ? (K_ + (p >> 1)) : (p >> 1);   // mu/sig interleave
        wfe[j] = __float2half(Wfe[(size_t)srow * H_ + col]);
    }
}

// ---------------------------------------------------------------------------
// Final-tick fe GEMM, split-K (fp32; runs once after the loop)
// ---------------------------------------------------------------------------
__global__ __launch_bounds__(256, 1)
void gemm_fe(const float* __restrict__ hmat,
             const float* __restrict__ Wfe,
             float* __restrict__ part)
{
    __shared__ float As[16][68];
    __shared__ float Bs[16][132];

    const int ks   = blockIdx.x;
    const int bm   = blockIdx.y * 64;
    const int koff = ks * KC;
    const int tid  = threadIdx.x;
    const int tx   = tid & 31;
    const int ty   = tid >> 5;

    float acc[8][4];
    #pragma unroll
    for (int i = 0; i < 8; i++)
        #pragma unroll
        for (int j = 0; j < 4; j++) acc[i][j] = 0.f;

    for (int k0 = 0; k0 < KC; k0 += 16) {
        {
            const int row = tid >> 2;
            const int c4  = (tid & 3) * 4;
            float4 v = *(const float4*)(hmat + (size_t)(bm + row) * H_ + koff + k0 + c4);
            As[c4 + 0][row] = v.x;  As[c4 + 1][row] = v.y;
            As[c4 + 2][row] = v.z;  As[c4 + 3][row] = v.w;
        }
        #pragma unroll
        for (int r = 0; r < 2; r++) {
            const int idx = tid + r * 256;
            const int rowb = idx >> 2;
            const int c4  = (idx & 3) * 4;
            float4 v = *(const float4*)(Wfe + (size_t)rowb * H_ + koff + k0 + c4);
            Bs[c4 + 0][rowb] = v.x;  Bs[c4 + 1][rowb] = v.y;
            Bs[c4 + 2][rowb] = v.z;  Bs[c4 + 3][rowb] = v.w;
        }
        __syncthreads();

        #pragma unroll
        for (int kk = 0; kk < 16; kk++) {
            float a[8], b[4];
            #pragma unroll
            for (int i = 0; i < 8; i++) a[i] = As[kk][ty + i * 8];
            #pragma unroll
            for (int j = 0; j < 4; j++) b[j] = Bs[kk][tx + j * 32];
            #pragma unroll
            for (int i = 0; i < 8; i++)
                #pragma unroll
                for (int j = 0; j < 4; j++)
                    acc[i][j] = fmaf(a[i], b[j], acc[i][j]);
        }
        __syncthreads();
    }

    #pragma unroll
    for (int i = 0; i < 8; i++) {
        const int m = bm + ty + i * 8;
        #pragma unroll
        for (int j = 0; j < 4; j++) {
            const int n = tx + j * 32;
            part[((size_t)ks * B_ + m) * (2 * K_) + n] = acc[i][j];
        }
    }
}

__global__ void z_kernel(const float* __restrict__ eps,
                         const float* __restrict__ bfe,
                         const float* __restrict__ part,
                         float* __restrict__ out,
                         int t)
{
    const int idx = blockIdx.x * blockDim.x + threadIdx.x;
    if (idx >= B_ * K_) return;
    const int b = idx / K_;
    const int k = idx - b * K_;

    float mu = bfe[k];
    float sr = bfe[k + K_];
    #pragma unroll 8
    for (int s = 0; s < NS; s++) {
        const float* p = part + ((size_t)s * B_ + b) * (2 * K_);
        mu += p[k];
        sr += p[k + K_];
    }

    const float xv  = sr - 5.f;
    const float sig = (xv > 20.f) ? xv : log1pf(expf(xv));
    const float e   = eps[((size_t)t * B_ + b) * K_ + k];
    const float z   = e * sig + mu;

    const size_t plane = (size_t)B_ * K_ * T_;
    const size_t o = ((size_t)b * K_ + k) * T_ + t;
    out[o]             = z;
    out[o + plane]     = mu;
    out[o + 2 * plane] = sig;
}

__global__ void hc_copy(const float* __restrict__ h,
                        const float* __restrict__ c,
                        float* __restrict__ out)
{
    const int idx = blockIdx.x * blockDim.x + threadIdx.x;
    if (idx >= B_ * H_) return;
    const size_t base = 3 * (size_t)B_ * K_ * T_;
    out[base + idx]           = h[idx];
    out[base + B_ * H_ + idx] = c[idx];
}

// ---------------------------------------------------------------------------
extern "C" void kernel_launch(void* const* d_in, const int* in_sizes, int n_in,
                              void* d_out, int out_size)
{
    const float* x   = (const float*)d_in[0];
    const float* eps = (const float*)d_in[1];
    const float* Wih = (const float*)d_in[2];
    const float* Whh = (const float*)d_in[3];
    const float* bih = (const float*)d_in[4];
    const float* bhh = (const float*)d_in[5];
    const float* Wfe = (const float*)d_in[6];
    const float* bfe = (const float*)d_in[7];
    float* out = (float*)d_out;

    __half *wih, *whh, *wfe, *x16, *h16;
    float *xg, *h2, *c, *fep, *bias;
    cudaGetSymbolAddress((void**)&wih,  d_wih);
    cudaGetSymbolAddress((void**)&whh,  d_whh);
    cudaGetSymbolAddress((void**)&wfe,  d_wfe);
    cudaGetSymbolAddress((void**)&x16,  d_x16);
    cudaGetSymbolAddress((void**)&h16,  d_h16);
    cudaGetSymbolAddress((void**)&xg,   d_xg);
    cudaGetSymbolAddress((void**)&h2,   d_h);
    cudaGetSymbolAddress((void**)&c,    d_c);
    cudaGetSymbolAddress((void**)&fep,  d_fep);
    cudaGetSymbolAddress((void**)&bias, d_bias);

    __half* h16_buf[2] = { h16, h16 + B_ * H_ };
    float*  h_buf[2]   = { h2,  h2  + B_ * H_ };

    // One-time host resources (streams/events; created before graph capture)
    static cudaStream_t s2 = nullptr;
    static cudaEvent_t  evFork, evB;
    if (s2 == nullptr) {
        cudaStreamCreateWithFlags(&s2, cudaStreamNonBlocking);
        cudaEventCreateWithFlags(&evFork, cudaEventDisableTiming);
        cudaEventCreateWithFlags(&evB,    cudaEventDisableTiming);
        cudaFuncSetAttribute(gemm_mma2,
                             cudaFuncAttributeMaxDynamicSharedMemorySize,
                             SMEM_TOTAL);
    }

    const dim3 gTc0(G_ / 128, B_ / 64);    // (64, 4)  xg GEMM + t=0 cell update
    const dim3 gTc1(GA / 128, B_ / 64);    // (65, 4)  recurrent GEMM + fused fe
    const dim3 gFe(NS, B_ / 64);           // final-tick fe
    const int  eltBlocks = (B_ * H_ + 255) / 256;
    const int  zBlocks   = (B_ * K_ + 255) / 256;

    // Prep A on stream 0
    const long long prepAN = (long long)NW + B_ * D_ + G_;
    prep_a<<<(int)((prepAN + 255) / 256), 256>>>(
        x, Wih, bih, bhh, wih, x16, bias);

    // Capture-legal fork: record on origin stream, side stream waits, then runs
    cudaEventRecord(evFork, 0);
    cudaStreamWaitEvent(s2, evFork, 0);
    const long long prepBN = (long long)NW + 2LL * K_ * H_;
    prep_b<<<(int)((prepBN + 255) / 256), 256, 0, s2>>>(Whh, Wfe, whh, wfe);
    cudaEventRecord(evB, s2);

    // xg GEMM + fused t=0 cell update (overlaps prep_b)
    gemm_mma2<<<gTc0, 256, SMEM_TOTAL>>>(x16, wih, nullptr,
                                         nullptr, bias, xg,
                                         h_buf[0], c, h16_buf[0],
                                         nullptr, nullptr, nullptr, 0, 0);

    // Join: recurrent chain needs whh/wfe
    cudaStreamWaitEvent(0, evB, 0);

    for (int t = 1; t < T_; t++) {
        // GEMM(t): gates(t) from h(t-1)  +  fused fe/z for tick t-1
        gemm_mma2<<<gTc1, 256, SMEM_TOTAL>>>(
            h16_buf[(t - 1) & 1], whh, wfe,
            xg, nullptr, nullptr,
            h_buf[t & 1], c, h16_buf[t & 1],
            eps, bfe, out, t - 1, 1);
    }

    // Final tick's fe/z (t = T-1) + (h, c) copy
    gemm_fe<<<gFe, 256>>>(h_buf[(T_ - 1) & 1], Wfe, fep);
    z_kernel<<<zBlocks, 256>>>(eps, bfe, fep, out, T_ - 1);
    hc_copy<<<eltBlocks, 256>>>(h_buf[(T_ - 1) & 1], c, out);
}

// round 16
// speedup vs baseline: 2.4994x; 1.0383x over previous
#include <cuda_runtime.h>
#include <cuda_fp16.h>
#include <cstdint>
#include <math.h>

// Problem dims (fixed by setup_inputs)
#define B_ 256
#define D_ 2048
#define H_ 2048
#define K_ 64
#define T_ 32
#define G_ 8192           // 4*H
#define GA 8320           // augmented N: 4*H + 2*K (fused fe columns)
#define NS 64             // split-K factor for the final-tick fe GEMM
#define KC (H_ / NS)      // 32

// ---------------------------------------------------------------------------
// Scratch (device globals; no runtime allocation allowed)
// Single-term fp16: both X and W rounded to fp16, fp32 accumulate.
// W_hh/W_ih rows GATE-INTERLEAVED: perm row p <- orig row (p&3)*H + (p>>2)
// W_fe rows MU/SIG-INTERLEAVED:    perm row p <- orig row (p&1)*K + (p>>1)
// h (fp32) and h (fp16) PING-PONG buffered across ticks.
// ---------------------------------------------------------------------------
__device__ __half d_wih[G_ * D_];
__device__ __half d_whh[G_ * H_];
__device__ __half d_wfe[2 * K_ * H_];
__device__ __half d_x16[B_ * D_];
__device__ __half d_h16[2][B_ * H_];
__device__ float d_bias[G_];               // permuted b_ih + b_hh
__device__ float d_xg[B_ * G_];            // permuted cols
__device__ float d_h [2][B_ * H_];
__device__ float d_c [B_ * H_];
__device__ float d_fep[NS * B_ * 2 * K_];

__device__ __forceinline__ uint32_t smem_to_u32(const void* p) {
    uint32_t a;
    asm("{ .reg .u64 t; cvta.to.shared.u64 t, %1; cvt.u32.u64 %0, t; }"
        : "=r"(a) : "l"(p));
    return a;
}

// mma.sync m16n8k16 fp16 -> fp32 accumulate (plain sm_80+ PTX)
#define MMA16816(c, a0, a1, a2, a3, b0, b1) \
    asm volatile( \
        "mma.sync.aligned.m16n8k16.row.col.f32.f16.f16.f32 " \
        "{%0,%1,%2,%3}, {%4,%5,%6,%7}, {%8,%9}, {%0,%1,%2,%3};" \
        : "+f"((c)[0]), "+f"((c)[1]), "+f"((c)[2]), "+f"((c)[3]) \
        : "r"(a0), "r"(a1), "r"(a2), "r"(a3), "r"(b0), "r"(b1))

#define LDSM4(r, addr) \
    asm volatile("ldmatrix.sync.aligned.m8n8.x4.shared.b16 {%0,%1,%2,%3}, [%4];" \
        : "=r"((r)[0]), "=r"((r)[1]), "=r"((r)[2]), "=r"((r)[3]) : "r"(addr))

// ---------------------------------------------------------------------------
// Tensor-core fp16 single-term GEMM:  C = X * W   (fp32 accum)
// CTA tile 64m x 128n, BK=64 (32 chunks -> half the sync/wait events of BK=32),
// 8 warps (warp = 32m x 32n), 3-stage cp.async.
// gate_mode=0: grid (64,4): writes xg[m,n]=acc+bias AND does t=0 cell update
// gate_mode=1: grid (65,4): n-tiles 0..63: g = acc + xg -> fused LSTM update;
//              n-tile 64 (bn=G_): fused fe -> z/mu/sig for tick tprev.
// ---------------------------------------------------------------------------
#define BK     64
#define NCH    (D_ / BK)       // 32 chunks
#define ROWB   144             // padded row pitch (64 fp16 = 128B data + 16 pad)
#define TILEA  (64 * ROWB)     // 9216  (X tile: 64 rows)
#define TILEW  (128 * ROWB)    // 18432 (W tile: 128 rows)
#define OFF_X  0
#define OFF_W  TILEA           // 9216
#define STAGEB (TILEA + TILEW) // 27648
#define NSTAGE 3
#define SMEM_TOTAL (NSTAGE * STAGEB)      // 82944

__global__ __launch_bounds__(256, 2)
void gemm_mma2(const __half* __restrict__ X,
               const __half* __restrict__ W,
               const __half* __restrict__ F,     // wfe (gate_mode=1)
               const float* __restrict__ xg,     // gate_mode=1 (read)
               const float* __restrict__ bias,   // gate_mode=0
               float* __restrict__ C,            // gate_mode=0 (xg write)
               float* __restrict__ h_out,
               float* __restrict__ c,
               __half* __restrict__ h16_out,
               const float* __restrict__ eps,    // fused fe
               const float* __restrict__ bfe,    // fused fe
               float* __restrict__ zout,         // fused fe
               int tprev,                        // fused fe tick index
               int gate_mode)
{
    extern __shared__ __align__(16) char smem[];
    const uint32_t sm0 = smem_to_u32(smem);

    const int tid  = threadIdx.x;
    const int lane = tid & 31;
    const int w    = tid >> 5;
    const int wy   = w & 1;          // m sub-tile (2 x 32)
    const int wx   = w >> 1;         // n sub-tile (4 x 32)
    const int q    = lane & 3;
    const int g    = lane >> 2;
    const int bn   = blockIdx.x * 128;
    const int bm   = blockIdx.y * 64;
    const int feTile = (bn >= G_);

    // Hoisted cp.async addressing: 6 (global ptr, smem offset) pairs
    // 1536 16B-loads per stage: [0,512) X tile, [512,1536) W tile
    const __half* gsrc[6];
    uint32_t dofs[6];
    {
        const __half* xs = X + (size_t)bm * D_;
        const __half* ws = feTile ? F : W + (size_t)bn * D_;
        #pragma unroll
        for (int i = 0; i < 6; i++) {
            const int idx = i * 256 + tid;
            if (idx < 512) {
                const int row = idx >> 3, qu = idx & 7;
                dofs[i] = OFF_X + row * ROWB + qu * 16;
                gsrc[i] = xs + (size_t)row * D_ + qu * 8;
            } else {
                const int j = idx - 512;
                const int row = j >> 3, qu = j & 7;
                dofs[i] = OFF_W + row * ROWB + qu * 16;
                gsrc[i] = ws + (size_t)row * D_ + qu * 8;
            }
        }
    }

    // ldmatrix per-lane addressing
    const int lrow = (lane & 7) + ((lane >> 3) & 1) * 8;
    const int colh = (lane >> 4) * 16;

    float acc[2][4][4];
    #pragma unroll
    for (int a = 0; a < 2; a++)
        #pragma unroll
        for (int b = 0; b < 4; b++)
            #pragma unroll
            for (int d = 0; d < 4; d++) acc[a][b][d] = 0.f;

#define ISSUE(st) do {                                                        \
    const uint32_t _stb = sm0 + (st) * STAGEB;                                \
    _Pragma("unroll")                                                         \
    for (int i = 0; i < 6; i++) {                                             \
        asm volatile("cp.async.cg.shared.global [%0], [%1], 16;"              \
                     :: "r"(_stb + dofs[i]), "l"(gsrc[i]));                   \
        gsrc[i] += BK;                                                        \
    }                                                                         \
    asm volatile("cp.async.commit_group;" ::: "memory");                      \
} while (0)

    ISSUE(0);
    ISSUE(1);

    int st = 0, st_issue = 2;
    for (int ch = 0; ch < NCH; ch++) {
        if (ch < NCH - 1) asm volatile("cp.async.wait_group 1;" ::: "memory");
        else              asm volatile("cp.async.wait_group 0;" ::: "memory");
        __syncthreads();
        if (ch + 2 < NCH) {
            ISSUE(st_issue);
            st_issue = st_issue + 1 >= NSTAGE ? 0 : st_issue + 1;
        }

        const uint32_t stb = sm0 + st * STAGEB;
        const uint32_t aBs = stb + OFF_X + (wy * 32 + lrow) * ROWB + colh;
        const uint32_t bBs = stb + OFF_W + (wx * 32 + lrow) * ROWB + colh;

        #pragma unroll
        for (int ks = 0; ks < 4; ks++) {       // 4 k16 steps per BK=64 chunk
            uint32_t ah[2][4], bh[2][4];
            #pragma unroll
            for (int mb = 0; mb < 2; mb++)
                LDSM4(ah[mb], aBs + mb * 16 * ROWB + ks * 32);
            #pragma unroll
            for (int t2 = 0; t2 < 2; t2++)
                LDSM4(bh[t2], bBs + t2 * 16 * ROWB + ks * 32);

            #pragma unroll
            for (int t2 = 0; t2 < 2; t2++)
                #pragma unroll
                for (int mb = 0; mb < 2; mb++) {
                    MMA16816(acc[mb][t2 * 2],     ah[mb][0], ah[mb][1], ah[mb][2], ah[mb][3], bh[t2][0], bh[t2][2]);
                    MMA16816(acc[mb][t2 * 2 + 1], ah[mb][0], ah[mb][1], ah[mb][2], ah[mb][3], bh[t2][1], bh[t2][3]);
                }
        }
        st = st + 1 >= NSTAGE ? 0 : st + 1;
        // next iteration's __syncthreads protects stage reuse
    }
#undef ISSUE

    // ---------------- Epilogues ----------------
    if (gate_mode == 1 && feTile) {
        // Fused fe/z epilogue: cols (2k, 2k+1) = (mu_k partial, sig_k partial)
        const size_t plane = (size_t)B_ * K_ * T_;
        #pragma unroll
        for (int mb = 0; mb < 2; mb++) {
            const int r0 = bm + wy * 32 + mb * 16 + g;
            #pragma unroll
            for (int j = 0; j < 4; j++) {
                const int col = wx * 32 + j * 8 + 2 * q;   // 0..127, even
                const int k   = col >> 1;
                const float bmu = bfe[k];
                const float bsr = bfe[K_ + k];
                #pragma unroll
                for (int rr = 0; rr < 2; rr++) {
                    const int   b  = r0 + rr * 8;
                    const float mu = acc[mb][j][rr * 2 + 0] + bmu;
                    const float xv = acc[mb][j][rr * 2 + 1] + bsr - 5.f;
                    const float sig = (xv > 20.f) ? xv : log1pf(expf(xv));
                    const float e  = eps[((size_t)tprev * B_ + b) * K_ + k];
                    const size_t o = ((size_t)b * K_ + k) * T_ + tprev;
                    zout[o]             = e * sig + mu;
                    zout[o + plane]     = mu;
                    zout[o + 2 * plane] = sig;
                }
            }
        }
        return;
    }

    // Gate epilogue (both modes). mode 0: v = acc + bias, write xg, cp = 0.
    //                             mode 1: v = acc + xg,   cp = c[idx].
    const int evn = (lane & 1) == 0;   // q even: holds (i,f); q odd: (g,o)
    #pragma unroll
    for (int mb = 0; mb < 2; mb++) {
        const int r0 = bm + wy * 32 + mb * 16 + g;
        #pragma unroll
        for (int j = 0; j < 4; j++) {
            const int n0 = bn + wx * 32 + j * 8 + 2 * q;
            float v0, v1, v2, v3;
            if (gate_mode == 0) {
                const float d0 = bias[n0], d1 = bias[n0 + 1];
                v0 = acc[mb][j][0] + d0;
                v1 = acc[mb][j][1] + d1;
                v2 = acc[mb][j][2] + d0;
                v3 = acc[mb][j][3] + d1;
                *(float2*)(C + (size_t)r0 * G_ + n0)       = make_float2(v0, v1);
                *(float2*)(C + (size_t)(r0 + 8) * G_ + n0) = make_float2(v2, v3);
            } else {
                const float2 p0 = *(const float2*)(xg + (size_t)r0 * G_ + n0);
                const float2 p1 = *(const float2*)(xg + (size_t)(r0 + 8) * G_ + n0);
                v0 = acc[mb][j][0] + p0.x;
                v1 = acc[mb][j][1] + p0.y;
                v2 = acc[mb][j][2] + p1.x;
                v3 = acc[mb][j][3] + p1.y;
            }

            const float s0 = __shfl_xor_sync(0xffffffffu, v0, 1);
            const float s1 = __shfl_xor_sync(0xffffffffu, v1, 1);
            const float s2 = __shfl_xor_sync(0xffffffffu, v2, 1);
            const float s3 = __shfl_xor_sync(0xffffffffu, v3, 1);

            // even lane handles row r0; odd lane handles row r0+8
            const int   row = evn ? r0 : r0 + 8;
            const float gi = evn ? v0 : s2;
            const float gf = evn ? v1 : s3;
            const float gg = evn ? s0 : v2;
            const float go = evn ? s1 : v3;

            const float iv = 1.f / (1.f + expf(-gi));
            const float gv = tanhf(gg);
            const float ov = 1.f / (1.f + expf(-go));

            const int  u   = (n0 >> 2);               // original hidden unit
            const int  idx = row * H_ + u;
            float cn;
            if (gate_mode == 0) {
                cn = iv * gv;                          // c0 = 0
            } else {
                const float fv = 1.f / (1.f + expf(-gf));
                cn = fv * c[idx] + iv * gv;
            }
            c[idx] = cn;
            const float hv = ov * tanhf(cn);
            h_out[idx] = hv;
            h16_out[idx] = __float2half(hv);
        }
    }
}

// ---------------------------------------------------------------------------
// Prep A (stream 0): wih -> fp16 (gate-permuted) + x -> fp16 + bias
// ---------------------------------------------------------------------------
#define NW (G_ * D_)
__global__ void prep_a(const float* __restrict__ x,
                       const float* __restrict__ Wih,
                       const float* __restrict__ bih,
                       const float* __restrict__ bhh,
                       __half* __restrict__ wih,
                       __half* __restrict__ x16,
                       float* __restrict__ bias)
{
    const long long i = (long long)blockIdx.x * blockDim.x + threadIdx.x;
    if (i < NW) {
        const int p   = (int)(i / D_);
        const int col = (int)(i - (long long)p * D_);
        const int srow = (p & 3) * H_ + (p >> 2);
        wih[i] = __float2half(Wih[(size_t)srow * D_ + col]);
    } else if (i < NW + B_ * D_) {
        const int j = (int)(i - NW);
        x16[j] = __float2half(x[j]);
    } else if (i < NW + B_ * D_ + G_) {
        const int p = (int)(i - NW - B_ * D_);
        const int o = (p & 3) * H_ + (p >> 2);
        bias[p] = bih[o] + bhh[o];
    }
}

// ---------------------------------------------------------------------------
// Prep B (side stream, overlapped with xg GEMM):
// whh -> fp16 (gate-permuted) + wfe -> fp16 (mu/sig-interleaved)
// ---------------------------------------------------------------------------
__global__ void prep_b(const float* __restrict__ Whh,
                       const float* __restrict__ Wfe,
                       __half* __restrict__ whh,
                       __half* __restrict__ wfe)
{
    const long long i = (long long)blockIdx.x * blockDim.x + threadIdx.x;
    if (i < NW) {
        const int p   = (int)(i / H_);
        const int col = (int)(i - (long long)p * H_);
        const int srow = (p & 3) * H_ + (p >> 2);
        whh[i] = __float2half(Whh[(size_t)srow * H_ + col]);
    } else if (i < NW + 2LL * K_ * H_) {
        const int j   = (int)(i - NW);
        const int p   = j / H_;          // 0..127
        const int col = j - p * H_;
        const int srow = (p & 1) ? (K_ + (p >> 1)) : (p >> 1);   // mu/sig interleave
        wfe[j] = __float2half(Wfe[(size_t)srow * H_ + col]);
    }
}

// ---------------------------------------------------------------------------
// Final-tick fe GEMM, split-K (fp32; runs once after the loop)
// ---------------------------------------------------------------------------
__global__ __launch_bounds__(256, 1)
void gemm_fe(const float* __restrict__ hmat,
             const float* __restrict__ Wfe,
             float* __restrict__ part)
{
    __shared__ float As[16][68];
    __shared__ float Bs[16][132];

    const int ks   = blockIdx.x;
    const int bm   = blockIdx.y * 64;
    const int koff = ks * KC;
    const int tid  = threadIdx.x;
    const int tx   = tid & 31;
    const int ty   = tid >> 5;

    float acc[8][4];
    #pragma unroll
    for (int i = 0; i < 8; i++)
        #pragma unroll
        for (int j = 0; j < 4; j++) acc[i][j] = 0.f;

    for (int k0 = 0; k0 < KC; k0 += 16) {
        {
            const int row = tid >> 2;
            const int c4  = (tid & 3) * 4;
            float4 v = *(const float4*)(hmat + (size_t)(bm + row) * H_ + koff + k0 + c4);
            As[c4 + 0][row] = v.x;  As[c4 + 1][row] = v.y;
            As[c4 + 2][row] = v.z;  As[c4 + 3][row] = v.w;
        }
        #pragma unroll
        for (int r = 0; r < 2; r++) {
            const int idx = tid + r * 256;
            const int rowb = idx >> 2;
            const int c4  = (idx & 3) * 4;
            float4 v = *(const float4*)(Wfe + (size_t)rowb * H_ + koff + k0 + c4);
            Bs[c4 + 0][rowb] = v.x;  Bs[c4 + 1][rowb] = v.y;
            Bs[c4 + 2][rowb] = v.z;  Bs[c4 + 3][rowb] = v.w;
        }
        __syncthreads();

        #pragma unroll
        for (int kk = 0; kk < 16; kk++) {
            float a[8], b[4];
            #pragma unroll
            for (int i = 0; i < 8; i++) a[i] = As[kk][ty + i * 8];
            #pragma unroll
            for (int j = 0; j < 4; j++) b[j] = Bs[kk][tx + j * 32];
            #pragma unroll
            for (int i = 0; i < 8; i++)
                #pragma unroll
                for (int j = 0; j < 4; j++)
                    acc[i][j] = fmaf(a[i], b[j], acc[i][j]);
        }
        __syncthreads();
    }

    #pragma unroll
    for (int i = 0; i < 8; i++) {
        const int m = bm + ty + i * 8;
        #pragma unroll
        for (int j = 0; j < 4; j++) {
            const int n = tx + j * 32;
            part[((size_t)ks * B_ + m) * (2 * K_) + n] = acc[i][j];
        }
    }
}

__global__ void z_kernel(const float* __restrict__ eps,
                         const float* __restrict__ bfe,
                         const float* __restrict__ part,
                         float* __restrict__ out,
                         int t)
{
    const int idx = blockIdx.x * blockDim.x + threadIdx.x;
    if (idx >= B_ * K_) return;
    const int b = idx / K_;
    const int k = idx - b * K_;

    float mu = bfe[k];
    float sr = bfe[k + K_];
    #pragma unroll 8
    for (int s = 0; s < NS; s++) {
        const float* p = part + ((size_t)s * B_ + b) * (2 * K_);
        mu += p[k];
        sr += p[k + K_];
    }

    const float xv  = sr - 5.f;
    const float sig = (xv > 20.f) ? xv : log1pf(expf(xv));
    const float e   = eps[((size_t)t * B_ + b) * K_ + k];
    const float z   = e * sig + mu;

    const size_t plane = (size_t)B_ * K_ * T_;
    const size_t o = ((size_t)b * K_ + k) * T_ + t;
    out[o]             = z;
    out[o + plane]     = mu;
    out[o + 2 * plane] = sig;
}

__global__ void hc_copy(const float* __restrict__ h,
                        const float* __restrict__ c,
                        float* __restrict__ out)
{
    const int idx = blockIdx.x * blockDim.x + threadIdx.x;
    if (idx >= B_ * H_) return;
    const size_t base = 3 * (size_t)B_ * K_ * T_;
    out[base + idx]           = h[idx];
    out[base + B_ * H_ + idx] = c[idx];
}

// ---------------------------------------------------------------------------
extern "C" void kernel_launch(void* const* d_in, const int* in_sizes, int n_in,
                              void* d_out, int out_size)
{
    const float* x   = (const float*)d_in[0];
    const float* eps = (const float*)d_in[1];
    const float* Wih = (const float*)d_in[2];
    const float* Whh = (const float*)d_in[3];
    const float* bih = (const float*)d_in[4];
    const float* bhh = (const float*)d_in[5];
    const float* Wfe = (const float*)d_in[6];
    const float* bfe = (const float*)d_in[7];
    float* out = (float*)d_out;

    __half *wih, *whh, *wfe, *x16, *h16;
    float *xg, *h2, *c, *fep, *bias;
    cudaGetSymbolAddress((void**)&wih,  d_wih);
    cudaGetSymbolAddress((void**)&whh,  d_whh);
    cudaGetSymbolAddress((void**)&wfe,  d_wfe);
    cudaGetSymbolAddress((void**)&x16,  d_x16);
    cudaGetSymbolAddress((void**)&h16,  d_h16);
    cudaGetSymbolAddress((void**)&xg,   d_xg);
    cudaGetSymbolAddress((void**)&h2,   d_h);
    cudaGetSymbolAddress((void**)&c,    d_c);
    cudaGetSymbolAddress((void**)&fep,  d_fep);
    cudaGetSymbolAddress((void**)&bias, d_bias);

    __half* h16_buf[2] = { h16, h16 + B_ * H_ };
    float*  h_buf[2]   = { h2,  h2  + B_ * H_ };

    // One-time host resources (streams/events; created before graph capture)
    static cudaStream_t s2 = nullptr;
    static cudaEvent_t  evFork, evB;
    if (s2 == nullptr) {
        cudaStreamCreateWithFlags(&s2, cudaStreamNonBlocking);
        cudaEventCreateWithFlags(&evFork, cudaEventDisableTiming);
        cudaEventCreateWithFlags(&evB,    cudaEventDisableTiming);
        cudaFuncSetAttribute(gemm_mma2,
                             cudaFuncAttributeMaxDynamicSharedMemorySize,
                             SMEM_TOTAL);
    }

    const dim3 gTc0(G_ / 128, B_ / 64);    // (64, 4)  xg GEMM + t=0 cell update
    const dim3 gTc1(GA / 128, B_ / 64);    // (65, 4)  recurrent GEMM + fused fe
    const dim3 gFe(NS, B_ / 64);           // final-tick fe
    const int  eltBlocks = (B_ * H_ + 255) / 256;
    const int  zBlocks   = (B_ * K_ + 255) / 256;

    // Prep A on stream 0
    const long long prepAN = (long long)NW + B_ * D_ + G_;
    prep_a<<<(int)((prepAN + 255) / 256), 256>>>(
        x, Wih, bih, bhh, wih, x16, bias);

    // Capture-legal fork: record on origin stream, side stream waits, then runs
    cudaEventRecord(evFork, 0);
    cudaStreamWaitEvent(s2, evFork, 0);
    const long long prepBN = (long long)NW + 2LL * K_ * H_;
    prep_b<<<(int)((prepBN + 255) / 256), 256, 0, s2>>>(Whh, Wfe, whh, wfe);
    cudaEventRecord(evB, s2);

    // xg GEMM + fused t=0 cell update (overlaps prep_b)
    gemm_mma2<<<gTc0, 256, SMEM_TOTAL>>>(x16, wih, nullptr,
                                         nullptr, bias, xg,
                                         h_buf[0], c, h16_buf[0],
                                         nullptr, nullptr, nullptr, 0, 0);

    // Join: recurrent chain needs whh/wfe
    cudaStreamWaitEvent(0, evB, 0);

    for (int t = 1; t < T_; t++) {
        // GEMM(t): gates(t) from h(t-1)  +  fused fe/z for tick t-1
        gemm_mma2<<<gTc1, 256, SMEM_TOTAL>>>(
            h16_buf[(t - 1) & 1], whh, wfe,
            xg, nullptr, nullptr,
            h_buf[t & 1], c, h16_buf[t & 1],
            eps, bfe, out, t - 1, 1);
    }

    // Final tick's fe/z (t = T-1) + (h, c) copy
    gemm_fe<<<gFe, 256>>>(h_buf[(T_ - 1) & 1], Wfe, fep);
    z_kernel<<<zBlocks, 256>>>(eps, bfe, fep, out, T_ - 1);
    hc_copy<<<eltBlocks, 256>>>(h_buf[(T_ - 1) & 1], c, out);
}